// round 15
// baseline (speedup 1.0000x reference)
#include <cuda_runtime.h>
#include <cuda_fp16.h>
#include <stdint.h>
#include <math.h>

#define NN   8
#define CC   256
#define HH   100
#define WWW  252
#define HWP  (HH*WWW)        // 25200
#define SS   2520
#define SSP  2560            // padded to 20*128
#define KCL  315
#define KNNK 10
#define NS   (NN*SS)
#define MAXC 8192            // max candidates per image
#define MARG 0.006f          // score-domain safety margin for approx pass
#define NTIL (SSP/128)       // 20

// ---------------- scratch ----------------
__device__ int   g_topidx[NS];
__device__ float g_conf[NS];
__device__ float g_tokens[NN*SSP*CC];                // pad rows stay static-zero
__device__ float g_sq[NS];
__device__ float g_dist[NN*SS*SS];                   // 203 MB
__device__ unsigned int g_distmax[NN];
__device__ float g_density[NS];
__device__ float g_noise[NS];
__device__ float g_cscore[NS];
__device__ int   g_centers[NN*KCL];
__device__ int   g_cluster[NS];
__device__ float g_allw[NN*KCL];
__device__ float g_merged[NN*KCL*CC];
__device__ int   g_isego[NN];
__device__ int   g_pixcl[NN*HWP];
__device__ __half g_tspH[2][NN*SSP*CC];              // fp16 2-way split of tokens
__device__ __half g_w1h[CC*CC];                      // fp16 w1 (approx pass)
__device__ float g_sapx[NN*HWP];                     // approx sigmoid
__device__ int   g_ncand[NN];
__device__ int   g_cand[NN*MAXC];
__device__ int   g_cslot[NN*HWP];
__device__ unsigned long long g_ckeys[NN*MAXC];      // compact exact keys
__device__ float g_xc[(size_t)NN*MAXC*CC];           // compact candidate columns
__device__ float g_knnpart[(size_t)NN*SS*NTIL*KNNK]; // per-tile partial 10-smallest (16 MB)

// ---------------- helpers ----------------
__device__ __forceinline__ void mma_f16(float* c, const uint32_t* a, const uint32_t* b) {
    asm volatile("mma.sync.aligned.m16n8k16.row.col.f32.f16.f16.f32 "
        "{%0,%1,%2,%3}, {%4,%5,%6,%7}, {%8,%9}, {%0,%1,%2,%3};"
        : "+f"(c[0]), "+f"(c[1]), "+f"(c[2]), "+f"(c[3])
        : "r"(a[0]), "r"(a[1]), "r"(a[2]), "r"(a[3]), "r"(b[0]), "r"(b[1]));
}
__device__ __forceinline__ uint32_t smem_u32(const void* p) {
    uint32_t a;
    asm("{ .reg .u64 t; cvta.to.shared.u64 t, %1; cvt.u32.u64 %0, t; }" : "=r"(a) : "l"(p));
    return a;
}
__device__ __forceinline__ void cp16(uint32_t saddr, const void* gaddr) {
    asm volatile("cp.async.cg.shared.global [%0], [%1], 16;" :: "r"(saddr), "l"(gaddr));
}
#define CP_COMMIT() asm volatile("cp.async.commit_group;" ::: "memory")
#define CP_WAIT(n)  asm volatile("cp.async.wait_group %0;" :: "n"(n) : "memory")
__device__ __forceinline__ unsigned int rotl32(unsigned int x, int r) {
    return (x << r) | (x >> (32 - r));
}
__device__ __forceinline__ void ins10(float* tp, float d) {
    if (d < tp[KNNK-1]) {
        tp[KNNK-1] = d;
        #pragma unroll
        for (int t = KNNK-1; t > 0; t--)
            if (tp[t] < tp[t-1]) { float m = tp[t-1]; tp[t-1] = tp[t]; tp[t] = m; }
    }
}

// ---------------- mega init kernel (vectorized) ----------------
__global__ void k_init(const float* __restrict__ w1, const int* __restrict__ rl, int nrec) {
    int i = blockIdx.x * blockDim.x + threadIdx.x;   // grid covers NN*KCL*CC/4
    if (i < NN*KCL*CC/4) ((float4*)g_merged)[i] = make_float4(0.f, 0.f, 0.f, 0.f);
    if (i < NN*HWP/4)    ((int4*)g_pixcl)[i] = make_int4(-1, -1, -1, -1);
    if (i < CC*CC/4) {
        float4 v = ((const float4*)w1)[i];
        __half2* dst = (__half2*)(&g_w1h[i*4]);
        dst[0] = __floats2half2_rn(v.x, v.y);
        dst[1] = __floats2half2_rn(v.z, v.w);
    }
    if (i < NN*KCL)    g_allw[i] = 0.f;
    if (i < NN)      { g_distmax[i] = 0u; g_ncand[i] = 0; }
    if (i == 0) {
        for (int t = 0; t < NN; t++) g_isego[t] = 0;
        int s = 0;
        for (int t = 0; t < nrec; t++) { if (s >= 0 && s < NN) g_isego[s] = 1; s += rl[t]; }
    }
    const int half = NS / 2;
    if (i < half) {   // threefry2x32 key=(0,1), counts (i, i+half)
        unsigned int x0 = (unsigned int)i, x1 = (unsigned int)(i + half);
        const unsigned int ks0 = 0u, ks1 = 1u, ks2 = 0x1BD11BDAu ^ 0u ^ 1u;
        x0 += ks0; x1 += ks1;
#define RG4(a0,a1,a2,a3) \
        x0 += x1; x1 = rotl32(x1,a0); x1 ^= x0; \
        x0 += x1; x1 = rotl32(x1,a1); x1 ^= x0; \
        x0 += x1; x1 = rotl32(x1,a2); x1 ^= x0; \
        x0 += x1; x1 = rotl32(x1,a3); x1 ^= x0;
        RG4(13,15,26,6)  x0 += ks1; x1 += ks2 + 1u;
        RG4(17,29,16,24) x0 += ks2; x1 += ks0 + 2u;
        RG4(13,15,26,6)  x0 += ks0; x1 += ks1 + 3u;
        RG4(17,29,16,24) x0 += ks1; x1 += ks2 + 4u;
        RG4(13,15,26,6)  x0 += ks2; x1 += ks0 + 5u;
#undef RG4
        g_noise[i]        = __uint_as_float((x0 >> 9) | 0x3f800000u) - 1.0f;
        g_noise[i + half] = __uint_as_float((x1 >> 9) | 0x3f800000u) - 1.0f;
    }
}

// ================= PASS 1: approx score via fp16 mma =================
#define KC  32
#define KP  40                 // padded smem row stride (halves)
__global__ __launch_bounds__(256)
void k_score_apx(const float* __restrict__ x, const float* __restrict__ b1,
                 const float* __restrict__ w2, const float* __restrict__ b2)
{
    __shared__ char sA[256*KP*2];
    __shared__ char sB[64*KP*2];
    __shared__ float sh_b1[CC], sh_w2[CC];
    __shared__ float red[64];
    int n  = blockIdx.y;
    int p0 = blockIdx.x * 64;
    int tid = threadIdx.x, lane = tid & 31, wid = tid >> 5;
    int g = lane >> 2, tg = lane & 3;
    int wm = wid & 3, wn = wid >> 2;
    const float* xn = x + (size_t)n * CC * HWP;

    if (tid < CC) { sh_b1[tid] = b1[tid]; sh_w2[tid] = w2[tid]; }
    if (tid < 64) red[tid] = 0.f;

    float acc[4][4][4];
    #pragma unroll
    for (int mt = 0; mt < 4; mt++)
        #pragma unroll
        for (int nt = 0; nt < 4; nt++)
            #pragma unroll
            for (int r = 0; r < 4; r++) acc[mt][nt][r] = 0.f;

    for (int c = 0; c < CC/KC; c++) {
        {   // A: w1 fp16 rows
            int d = tid;
            const uint4* src = (const uint4*)(&g_w1h[d*CC + c*KC]);
            uint4* dst = (uint4*)(sA + d*(KP*2));
            dst[0] = src[0]; dst[1] = src[1]; dst[2] = src[2]; dst[3] = src[3];
        }
        {   // B: x fp32 -> fp16 transposed; row-pair loads -> half2 stores
            int kp = tid >> 4;      // 0..15 -> k = 2*kp
            int pq = tid & 15;
            int p  = p0 + pq*4;
            int kg = c*KC + 2*kp;
            const float* r0 = xn + (size_t)kg * HWP + p;
            const float* r1 = r0 + HWP;
            float v0[4], v1[4];
            if (p + 4 <= HWP) {
                float4 a = *(const float4*)r0; v0[0]=a.x; v0[1]=a.y; v0[2]=a.z; v0[3]=a.w;
                float4 bq = *(const float4*)r1; v1[0]=bq.x; v1[1]=bq.y; v1[2]=bq.z; v1[3]=bq.w;
            } else {
                #pragma unroll
                for (int j = 0; j < 4; j++) {
                    v0[j] = (p+j < HWP) ? r0[j] : 0.f;
                    v1[j] = (p+j < HWP) ? r1[j] : 0.f;
                }
            }
            #pragma unroll
            for (int j = 0; j < 4; j++) {
                __half2 h = __floats2half2_rn(v0[j], v1[j]);
                *(__half2*)(sB + (pq*4+j)*(KP*2) + (2*kp)*2) = h;
            }
        }
        __syncthreads();
        #pragma unroll
        for (int ks = 0; ks < 2; ks++) {
            uint32_t af[4][4], bf[4][2];
            const char* Ab = sA + ks*32 + tg*4;
            #pragma unroll
            for (int mt = 0; mt < 4; mt++) {
                const char* pA = Ab + (wm*64 + mt*16 + g)*(KP*2);
                af[mt][0] = *(const uint32_t*)pA;
                af[mt][1] = *(const uint32_t*)(pA + 8*(KP*2));
                af[mt][2] = *(const uint32_t*)(pA + 16);
                af[mt][3] = *(const uint32_t*)(pA + 8*(KP*2) + 16);
            }
            const char* Bb = sB + ks*32 + tg*4;
            #pragma unroll
            for (int nt = 0; nt < 4; nt++) {
                const char* pB = Bb + (wn*32 + nt*8 + g)*(KP*2);
                bf[nt][0] = *(const uint32_t*)pB;
                bf[nt][1] = *(const uint32_t*)(pB + 16);
            }
            #pragma unroll
            for (int mt = 0; mt < 4; mt++)
                #pragma unroll
                for (int nt = 0; nt < 4; nt++)
                    mma_f16(acc[mt][nt], af[mt], bf[nt]);
        }
        __syncthreads();
    }

    float v[4][2];
    #pragma unroll
    for (int nt = 0; nt < 4; nt++) { v[nt][0] = 0.f; v[nt][1] = 0.f; }
    #pragma unroll
    for (int mt = 0; mt < 4; mt++) {
        int d0 = wm*64 + mt*16 + g;
        float hb0 = sh_b1[d0],   hw0 = sh_w2[d0];
        float hb1 = sh_b1[d0+8], hw1 = sh_w2[d0+8];
        #pragma unroll
        for (int nt = 0; nt < 4; nt++) {
            float h;
            h = acc[mt][nt][0] + hb0; v[nt][0] += (h > 0.f ? h : 0.f) * hw0;
            h = acc[mt][nt][1] + hb0; v[nt][1] += (h > 0.f ? h : 0.f) * hw0;
            h = acc[mt][nt][2] + hb1; v[nt][0] += (h > 0.f ? h : 0.f) * hw1;
            h = acc[mt][nt][3] + hb1; v[nt][1] += (h > 0.f ? h : 0.f) * hw1;
        }
    }
    #pragma unroll
    for (int nt = 0; nt < 4; nt++)
        #pragma unroll
        for (int par = 0; par < 2; par++) {
            float s = v[nt][par];
            s += __shfl_xor_sync(0xFFFFFFFFu, s, 4);
            s += __shfl_xor_sync(0xFFFFFFFFu, s, 8);
            s += __shfl_xor_sync(0xFFFFFFFFu, s, 16);
            v[nt][par] = s;
        }
    if (lane < 4) {
        #pragma unroll
        for (int nt = 0; nt < 4; nt++) {
            atomicAdd(&red[wn*32 + nt*8 + lane*2 + 0], v[nt][0]);
            atomicAdd(&red[wn*32 + nt*8 + lane*2 + 1], v[nt][1]);
        }
    }
    __syncthreads();
    if (tid < 64) {
        int p = p0 + tid;
        if (p < HWP) {
            float z = red[tid] + b2[0];
            g_sapx[(size_t)n*HWP + p] = 1.f / (1.f + expf(-z));
        }
    }
}

// ---------------- threshold + PIXEL-ORDERED candidate compaction ----------------
__global__ __launch_bounds__(1024)
void k_thresh_cand(const float* __restrict__ dis) {
    int b = blockIdx.x;
    __shared__ unsigned int hist[8][256], histsum[256];
    __shared__ unsigned int sh_prefix;
    __shared__ int sh_R;
    __shared__ int warpsum[32];
    __shared__ int sh_base;
    int tid = threadIdx.x, lane = tid & 31, wid = tid >> 5;
    int wid8 = wid & 7;
    if (tid == 0) { sh_prefix = 0u; sh_R = SS; sh_base = 0; }
    for (int byte = 3; byte >= 0; byte--) {
        for (int i = tid; i < 8*256; i += 1024) ((unsigned int*)hist)[i] = 0u;
        __syncthreads();
        int shift = byte * 8;
        unsigned int pref = sh_prefix;
        for (int i = tid; i < HWP; i += 1024) {
            float vlo = fmaxf(g_sapx[(size_t)b*HWP + i] - MARG, 0.f) * dis[(size_t)b*HWP + i];
            unsigned int k = __float_as_uint(vlo);
            if (byte == 3 || (k >> (shift+8)) == (pref >> (shift+8)))
                atomicAdd(&hist[wid8][(k >> shift) & 0xFFu], 1u);
        }
        __syncthreads();
        if (tid < 256) {
            unsigned int s = 0;
            #pragma unroll
            for (int w = 0; w < 8; w++) s += hist[w][tid];
            histsum[tid] = s;
        }
        __syncthreads();
        if (tid == 0) {
            int R = sh_R; long long cum = 0; int chosen = 0;
            for (int v = 255; v >= 0; v--) {
                cum += histsum[v];
                if (cum >= R) { chosen = v; sh_R = R - (int)(cum - histsum[v]); break; }
            }
            sh_prefix = pref | ((unsigned int)chosen << shift);
        }
        __syncthreads();
    }
    unsigned int T = sh_prefix;
    // ordered compaction: chunks of 1024 consecutive pixels, ballot + block scan
    for (int base = 0; base < HWP; base += 1024) {
        int p = base + tid;
        bool c = false;
        size_t i = (size_t)b*HWP + p;
        if (p < HWP) {
            float hi = (g_sapx[i] + MARG) * dis[i];
            c = (__float_as_uint(hi) >= T);
        }
        unsigned int bal = __ballot_sync(0xFFFFFFFFu, c);
        int wr = __popc(bal & ((1u << lane) - 1u));
        if (lane == 0) warpsum[wid] = __popc(bal);
        __syncthreads();
        if (tid < 32) {
            int v2 = warpsum[tid];
            #pragma unroll
            for (int off = 1; off < 32; off <<= 1) {
                int u = __shfl_up_sync(0xFFFFFFFFu, v2, off);
                if ((int)tid >= off) v2 += u;
            }
            warpsum[tid] = v2;   // inclusive scan
        }
        __syncthreads();
        int woff = (wid == 0) ? 0 : warpsum[wid - 1];
        if (c) {
            int slot = sh_base + woff + wr;
            if (slot < MAXC) { g_cand[b*MAXC + slot] = p; g_cslot[i] = slot; }
        }
        __syncthreads();
        if (tid == 0) sh_base += warpsum[31];
        __syncthreads();
    }
    if (tid == 0) g_ncand[b] = sh_base;
}

// ---------------- gather candidate columns compact (one block per candidate) ----------------
__global__ void k_gx(const float* __restrict__ x) {
    int b = blockIdx.y, s = blockIdx.x, c = threadIdx.x;
    int nc = min(g_ncand[b], MAXC);
    if (s >= nc) return;
    int pix = g_cand[b*MAXC + s];
    g_xc[((size_t)b*MAXC + s)*CC + c] = x[((size_t)b*CC + c)*HWP + pix];
}

// ================= PASS 2: exact fp32 SIMT score on candidates =================
__global__ __launch_bounds__(256, 2)
void k_score_exact(const float* __restrict__ w1, const float* __restrict__ b1,
                   const float* __restrict__ w2, const float* __restrict__ b2,
                   const float* __restrict__ dis)
{
    int b  = blockIdx.y;
    int c0 = blockIdx.x * 64;
    int nc = min(g_ncand[b], MAXC);
    if (c0 >= nc) return;
    __shared__ float As[KC][CC];
    __shared__ float Bs[KC][64];
    __shared__ float red[16][64];
    __shared__ int   sh_pix[64];
    int tid = threadIdx.x;
    int tx = tid & 15, ty = tid >> 4;
    if (tid < 64) sh_pix[tid] = (c0 + tid < nc) ? g_cand[b*MAXC + c0 + tid] : -1;

    float acc[16][4];
    #pragma unroll
    for (int r = 0; r < 16; r++)
        #pragma unroll
        for (int j = 0; j < 4; j++) acc[r][j] = 0.f;

    for (int k0 = 0; k0 < CC; k0 += KC) {
        for (int t = tid; t < CC * (KC/4); t += 256) {
            int d  = t >> 3, kq = t & 7;
            float4 v = *(const float4*)(w1 + (size_t)d * CC + k0 + kq*4);
            As[kq*4+0][d] = v.x; As[kq*4+1][d] = v.y;
            As[kq*4+2][d] = v.z; As[kq*4+3][d] = v.w;
        }
        {
            int j = tid >> 2, kq2 = (tid & 3) * 2;
            bool ok = (c0 + j < nc);
            #pragma unroll
            for (int q = 0; q < 2; q++) {
                int kq = kq2 + q;
                float4 v = ok ? *(const float4*)(&g_xc[((size_t)b*MAXC + c0 + j)*CC + k0 + kq*4])
                              : make_float4(0.f,0.f,0.f,0.f);
                Bs[kq*4+0][j] = v.x; Bs[kq*4+1][j] = v.y;
                Bs[kq*4+2][j] = v.z; Bs[kq*4+3][j] = v.w;
            }
        }
        __syncthreads();
        #pragma unroll
        for (int kk = 0; kk < KC; kk++) {
            float a[16];
            *(float4*)(a+0)  = *(float4*)&As[kk][ty*16+0];
            *(float4*)(a+4)  = *(float4*)&As[kk][ty*16+4];
            *(float4*)(a+8)  = *(float4*)&As[kk][ty*16+8];
            *(float4*)(a+12) = *(float4*)&As[kk][ty*16+12];
            float4 bf = *(float4*)&Bs[kk][tx*4];
            float bb[4] = {bf.x, bf.y, bf.z, bf.w};
            #pragma unroll
            for (int r = 0; r < 16; r++)
                #pragma unroll
                for (int j = 0; j < 4; j++) acc[r][j] += a[r] * bb[j];
        }
        __syncthreads();
    }
    float part[4] = {0.f, 0.f, 0.f, 0.f};
    #pragma unroll
    for (int r = 0; r < 16; r++) {
        int d = ty*16 + r;
        float bbv = b1[d], wwv = w2[d];
        #pragma unroll
        for (int j = 0; j < 4; j++) {
            float h = acc[r][j] + bbv;
            h = h > 0.f ? h : 0.f;
            part[j] += h * wwv;
        }
    }
    #pragma unroll
    for (int j = 0; j < 4; j++) red[ty][tx*4+j] = part[j];
    __syncthreads();
    if (tid < 64) {
        int pix = sh_pix[tid];
        if (pix >= 0) {
            float s = 0.f;
            #pragma unroll
            for (int r = 0; r < 16; r++) s += red[r][tid];
            float z  = s + b2[0];
            float sc = 1.f / (1.f + expf(-z));
            sc *= dis[(size_t)b*HWP + pix];
            unsigned int bits = __float_as_uint(sc);
            g_ckeys[b*MAXC + c0 + tid] =
                ((unsigned long long)bits << 32) | (unsigned int)(~(unsigned int)pix);
        }
    }
}

// ---------------- bitonic ascending sort ----------------
__device__ __forceinline__ void bitonic_asc(unsigned long long* buf, int n, int tid, int nth) {
    for (int k2 = 2; k2 <= n; k2 <<= 1)
        for (int j = k2 >> 1; j > 0; j >>= 1) {
            __syncthreads();
            for (int i = tid; i < n; i += nth) {
                int ixj = i ^ j;
                if (ixj > i) {
                    unsigned long long a = buf[i], b = buf[ixj];
                    bool up = ((i & k2) == 0);
                    if (up ? (a > b) : (a < b)) { buf[i] = b; buf[ixj] = a; }
                }
            }
        }
    __syncthreads();
}

// ---------------- exact top-S over compact candidate keys ----------------
__global__ __launch_bounds__(1024)
void k_topk_c() {
    int b = blockIdx.x;
    int nc = min(g_ncand[b], MAXC);
    const unsigned long long* keys = g_ckeys + (size_t)b * MAXC;
    __shared__ unsigned int hist[8][256], histsum[256];
    __shared__ unsigned long long sh_prefix;
    __shared__ int sh_R, sh_cnt;
    __shared__ unsigned long long buf[4096];
    int tid = threadIdx.x, wid8 = (tid >> 5) & 7;
    if (tid == 0) { sh_prefix = 0ULL; sh_R = SS; sh_cnt = 0; }

    for (int byte = 7; byte >= 0; byte--) {
        for (int i = tid; i < 8*256; i += 1024) ((unsigned int*)hist)[i] = 0u;
        __syncthreads();
        int shift = byte * 8;
        unsigned long long pref = sh_prefix;
        for (int i = tid; i < nc; i += 1024) {
            unsigned long long k = keys[i];
            if (byte == 7 || (k >> (shift+8)) == (pref >> (shift+8)))
                atomicAdd(&hist[wid8][(unsigned)(k >> shift) & 0xFFu], 1u);
        }
        __syncthreads();
        if (tid < 256) {
            unsigned int s = 0;
            #pragma unroll
            for (int w = 0; w < 8; w++) s += hist[w][tid];
            histsum[tid] = s;
        }
        __syncthreads();
        if (tid == 0) {
            int R = sh_R; long long cum = 0; int chosen = 0;
            for (int v = 255; v >= 0; v--) {
                cum += histsum[v];
                if (cum >= R) { chosen = v; sh_R = R - (int)(cum - histsum[v]); break; }
            }
            sh_prefix = pref | ((unsigned long long)chosen << shift);
        }
        __syncthreads();
    }
    unsigned long long T = sh_prefix;
    for (int i = tid; i < 4096; i += 1024) buf[i] = 0ULL;
    __syncthreads();
    for (int i = tid; i < nc; i += 1024) {
        unsigned long long k = keys[i];
        if (k >= T) { int pos = atomicAdd(&sh_cnt, 1); if (pos < 4096) buf[pos] = k; }
    }
    __syncthreads();
    bitonic_asc(buf, 4096, tid, 1024);
    for (int s = tid; s < SS; s += 1024) {
        unsigned long long k = buf[4095 - s];
        g_topidx[b*SS + s] = (int)(~(unsigned int)k);
        g_conf  [b*SS + s] = __uint_as_float((unsigned int)(k >> 32));
    }
}

// ---------------- gather (compact) + layernorm + *conf + fp16x2 split + sumsq ----------------
__global__ void k_gather_ln() {
    int b = blockIdx.y, s = blockIdx.x;
    int c = threadIdx.x;
    __shared__ float sh[256];
    int   pix  = g_topidx[b*SS + s];
    float conf = g_conf[b*SS + s];
    int   slot = g_cslot[b*HWP + pix];
    float v = g_xc[((size_t)b*MAXC + slot)*CC + c];

    sh[c] = v; __syncthreads();
    for (int st = 128; st > 0; st >>= 1) { if (c < st) sh[c] += sh[c+st]; __syncthreads(); }
    float mu = sh[0] * (1.f/256.f);
    __syncthreads();
    float dv = v - mu;
    sh[c] = dv * dv; __syncthreads();
    for (int st = 128; st > 0; st >>= 1) { if (c < st) sh[c] += sh[c+st]; __syncthreads(); }
    float var = sh[0] * (1.f/256.f);
    __syncthreads();
    float t = dv / sqrtf(var + 1e-5f) * conf;
    size_t o = ((size_t)b*SSP + s)*CC + c;
    g_tokens[o] = t;
    __half t1 = __float2half(t);
    __half t2 = __float2half(t - __half2float(t1));
    g_tspH[0][o] = t1; g_tspH[1][o] = t2;
    sh[c] = t * t; __syncthreads();
    for (int st = 128; st > 0; st >>= 1) { if (c < st) sh[c] += sh[c+st]; __syncthreads(); }
    if (c == 0) g_sq[b*SS + s] = sh[0];
}

// ================= distance GEMM: fp16x2 (3 terms), cp.async, fused partial-KNN =================
#define DI_T  (128*KP*2)             // 10240 B per split tile
#define DI_STG (4*DI_T)              // 40960 per stage
#define DI_SMEM (2*DI_STG)           // 81920 (Dt 66048 + sm_part 10240 fit)
#define NPAIR (NTIL*(NTIL+1)/2)      // 210

__global__ __launch_bounds__(256)
void k_dist_mma() {
    int b = blockIdx.y;
    int t = blockIdx.x;
    int bi = (int)((sqrtf(8.f*t + 1.f) - 1.f) * 0.5f);
    while ((bi+1)*(bi+2)/2 <= t) bi++;
    while (bi*(bi+1)/2 > t) bi--;
    int bj = t - bi*(bi+1)/2;
    extern __shared__ char smp[];
    __shared__ float s_sqi[128], s_sqj[128], wmaxs[8];
    int tid = threadIdx.x, lane = tid & 31, wid = tid >> 5;
    int g = lane >> 2, tg = lane & 3;
    int wm = wid & 1, wn = wid >> 1;
    int i0 = bi * 128, j0 = bj * 128;
    uint32_t sbase = smem_u32(smp);

    if (tid < 128)      s_sqi[tid]     = (i0 + tid     < SS) ? g_sq[b*SS + i0 + tid]     : 0.f;
    else                s_sqj[tid-128] = (j0 + tid-128 < SS) ? g_sq[b*SS + j0 + tid-128] : 0.f;

    int r = tid & 127, side = tid >> 7;
    int grow = (side ? j0 : i0) + r;
    #pragma unroll
    for (int s = 0; s < 2; s++) {
        const char* src = (const char*)(&g_tspH[s][((size_t)(b*SSP + grow))*CC]);
        uint32_t dst = sbase + (side*2 + s)*DI_T + r*(KP*2);
        #pragma unroll
        for (int q = 0; q < 4; q++) cp16(dst + q*16, src + q*16);
    }
    CP_COMMIT();

    float acc[4][4][4];
    #pragma unroll
    for (int mt = 0; mt < 4; mt++)
        #pragma unroll
        for (int nt = 0; nt < 4; nt++)
            #pragma unroll
            for (int rr = 0; rr < 4; rr++) acc[mt][nt][rr] = 0.f;

    const int TA[3] = {0,0,1};
    const int TB[3] = {0,1,0};

    for (int c = 0; c < CC/KC; c++) {
        int stg = c & 1;
        if (c + 1 < CC/KC) {
            int nstg = stg ^ 1;
            #pragma unroll
            for (int s = 0; s < 2; s++) {
                const char* src = (const char*)(&g_tspH[s][((size_t)(b*SSP + grow))*CC + (c+1)*KC]);
                uint32_t dst = sbase + nstg*DI_STG + (side*2 + s)*DI_T + r*(KP*2);
                #pragma unroll
                for (int q = 0; q < 4; q++) cp16(dst + q*16, src + q*16);
            }
            CP_COMMIT();
            CP_WAIT(1);
        } else {
            CP_WAIT(0);
        }
        __syncthreads();
        const char* base = smp + stg*DI_STG;
        #pragma unroll
        for (int term = 0; term < 3; term++) {
            int sa = TA[term], sb = TB[term];
            #pragma unroll
            for (int ks = 0; ks < 2; ks++) {
                uint32_t af[4][4], bf[4][2];
                const char* Ab = base + sa*DI_T + ks*32 + tg*4;
                #pragma unroll
                for (int mt = 0; mt < 4; mt++) {
                    const char* pA = Ab + (wm*64 + mt*16 + g)*(KP*2);
                    af[mt][0] = *(const uint32_t*)pA;
                    af[mt][1] = *(const uint32_t*)(pA + 8*(KP*2));
                    af[mt][2] = *(const uint32_t*)(pA + 16);
                    af[mt][3] = *(const uint32_t*)(pA + 8*(KP*2) + 16);
                }
                const char* Bb = base + (2 + sb)*DI_T + ks*32 + tg*4;
                #pragma unroll
                for (int nt = 0; nt < 4; nt++) {
                    const char* pB = Bb + (wn*32 + nt*8 + g)*(KP*2);
                    bf[nt][0] = *(const uint32_t*)pB;
                    bf[nt][1] = *(const uint32_t*)(pB + 16);
                }
                #pragma unroll
                for (int mt = 0; mt < 4; mt++)
                    #pragma unroll
                    for (int nt = 0; nt < 4; nt++)
                        mma_f16(acc[mt][nt], af[mt], bf[nt]);
            }
        }
        __syncthreads();
    }

    float* Dt = (float*)smp;   // [128][129] = 66048 B
    float* sm_part = (float*)(smp + 66048);  // [256][10] = 10240 B
    float tmax = 0.f;
    #pragma unroll
    for (int mt = 0; mt < 4; mt++) {
        #pragma unroll
        for (int nt = 0; nt < 4; nt++) {
            int il0 = wm*64 + mt*16 + g;
            int jl0 = wn*32 + nt*8 + tg*2;
            #pragma unroll
            for (int rr = 0; rr < 4; rr++) {
                int il = il0 + ((rr >> 1) ? 8 : 0);
                int jl = jl0 + (rr & 1);
                float d2 = s_sqi[il] + s_sqj[jl] - 2.f * acc[mt][nt][rr];
                float d  = sqrtf(fmaxf(d2, 1e-12f)) * 0.0625f;
                Dt[il*129 + jl] = d;
                if (i0 + il < SS && j0 + jl < SS) tmax = fmaxf(tmax, d);
            }
        }
    }
    __syncthreads();
    for (int idx = tid; idx < 128*128; idx += 256) {
        int il = idx >> 7, jj = idx & 127;
        int i = i0 + il, j = j0 + jj;
        if (i < SS && j < SS) g_dist[((size_t)b*SS + i)*SS + j] = Dt[il*129 + jj];
    }
    if (bi != bj) {
        for (int idx = tid; idx < 128*128; idx += 256) {
            int jl = idx >> 7, ii = idx & 127;
            int i = i0 + ii, j = j0 + jl;
            if (i < SS) g_dist[((size_t)b*SS + j)*SS + i] = Dt[ii*129 + jl];
        }
    }

    // ---- fused partial top-10: i-side rows, tile column bj ----
    {
        int row = tid >> 1, half = tid & 1;
        float tp[KNNK];
        #pragma unroll
        for (int q = 0; q < KNNK; q++) tp[q] = 3.4e38f;
        if (i0 + row < SS) {
            const float* drow = Dt + row*129 + half*64;
            for (int jj = 0; jj < 64; jj++) {
                int jl = half*64 + jj;
                float d = (j0 + jl < SS) ? drow[jj] : 3.4e38f;
                ins10(tp, d);
            }
        }
        #pragma unroll
        for (int q = 0; q < KNNK; q++) sm_part[tid*KNNK + q] = tp[q];
        __syncwarp();
        if (half == 0 && i0 + row < SS) {
            const float* a  = &sm_part[tid*KNNK];
            const float* bq = &sm_part[(tid+1)*KNNK];
            float* dst = &g_knnpart[(((size_t)b*SS + i0 + row)*NTIL + bj)*KNNK];
            int ia = 0, ib = 0;
            #pragma unroll
            for (int q = 0; q < KNNK; q++) {
                float va = a[ia], vb = bq[ib];
                if (va <= vb) { dst[q] = va; ia++; } else { dst[q] = vb; ib++; }
            }
        }
    }
    // ---- mirror side: j-rows, tile column bi (only off-diagonal) ----
    if (bi != bj) {
        __syncthreads();
        int row = tid >> 1, half = tid & 1;   // row = jl ; j always < SS (bj <= 18)
        float tp[KNNK];
        #pragma unroll
        for (int q = 0; q < KNNK; q++) tp[q] = 3.4e38f;
        for (int ii = 0; ii < 64; ii++) {
            int il = half*64 + ii;
            float d = (i0 + il < SS) ? Dt[il*129 + row] : 3.4e38f;
            ins10(tp, d);
        }
        #pragma unroll
        for (int q = 0; q < KNNK; q++) sm_part[tid*KNNK + q] = tp[q];
        __syncwarp();
        if (half == 0) {
            const float* a  = &sm_part[tid*KNNK];
            const float* bq = &sm_part[(tid+1)*KNNK];
            float* dst = &g_knnpart[(((size_t)b*SS + j0 + row)*NTIL + bi)*KNNK];
            int ia = 0, ib = 0;
            #pragma unroll
            for (int q = 0; q < KNNK; q++) {
                float va = a[ia], vb = bq[ib];
                if (va <= vb) { dst[q] = va; ia++; } else { dst[q] = vb; ib++; }
            }
        }
    }

    #pragma unroll
    for (int off = 16; off; off >>= 1) tmax = fmaxf(tmax, __shfl_xor_sync(0xFFFFFFFFu, tmax, off));
    if (lane == 0) wmaxs[wid] = tmax;
    __syncthreads();
    if (tid == 0) {
        float m = 0.f;
        #pragma unroll
        for (int w = 0; w < 8; w++) m = fmaxf(m, wmaxs[w]);
        atomicMax(&g_distmax[b], __float_as_uint(m));
    }
}

// ---------------- KNN density: merge per-tile partials (16 MB read) ----------------
__global__ void k_knn_merge() {
    int gw = (blockIdx.x * blockDim.x + threadIdx.x) >> 5;
    int lane = threadIdx.x & 31;
    if (gw >= NS) return;
    const float* part = g_knnpart + (size_t)gw * (NTIL*KNNK);
    float top[KNNK];
    #pragma unroll
    for (int t = 0; t < KNNK; t++) top[t] = 3.4e38f;
    for (int idx = lane; idx < NTIL*KNNK; idx += 32) {
        float d = part[idx];
        ins10(top, d);
    }
    int ptr = 0;
    float sumsq = 0.f;
    for (int t = 0; t < KNNK; t++) {
        float cand = (ptr < KNNK) ? top[ptr] : 3.4e38f;
        float m = cand;
        #pragma unroll
        for (int off = 16; off; off >>= 1) m = fminf(m, __shfl_xor_sync(0xFFFFFFFFu, m, off));
        sumsq += m * m;
        unsigned bal = __ballot_sync(0xFFFFFFFFu, cand == m);
        int src = __ffs(bal) - 1;
        if (lane == src) ptr++;
    }
    if (lane == 0)
        g_density[gw] = expf(-(sumsq * (1.f/KNNK))) + g_noise[gw] * 1e-6f;
}

// ---------------- parent distance + cscore (warp per row, float4, 2-way ILP) ----------------
__global__ void k_parent() {
    int gw = (blockIdx.x * blockDim.x + threadIdx.x) >> 5;
    int lane = threadIdx.x & 31;
    if (gw >= NS) return;
    int b = gw / SS, i = gw % SS;
    float di   = g_density[gw];
    float dmax = __uint_as_float(g_distmax[b]);
    const float4* row4  = (const float4*)(g_dist + ((size_t)b*SS + i)*SS);
    const float4* dens4 = (const float4*)(g_density + b*SS);
    float acc0 = dmax, acc1 = dmax;
    int j4 = lane;
    for (; j4 + 32 < SS/4; j4 += 64) {
        float4 dv0 = dens4[j4],      rv0 = row4[j4];
        float4 dv1 = dens4[j4 + 32], rv1 = row4[j4 + 32];
        if (dv0.x > di) acc0 = fminf(acc0, rv0.x);
        if (dv0.y > di) acc0 = fminf(acc0, rv0.y);
        if (dv0.z > di) acc0 = fminf(acc0, rv0.z);
        if (dv0.w > di) acc0 = fminf(acc0, rv0.w);
        if (dv1.x > di) acc1 = fminf(acc1, rv1.x);
        if (dv1.y > di) acc1 = fminf(acc1, rv1.y);
        if (dv1.z > di) acc1 = fminf(acc1, rv1.z);
        if (dv1.w > di) acc1 = fminf(acc1, rv1.w);
    }
    if (j4 < SS/4) {
        float4 dv = dens4[j4], rv = row4[j4];
        if (dv.x > di) acc0 = fminf(acc0, rv.x);
        if (dv.y > di) acc0 = fminf(acc0, rv.y);
        if (dv.z > di) acc0 = fminf(acc0, rv.z);
        if (dv.w > di) acc0 = fminf(acc0, rv.w);
    }
    float acc = fminf(acc0, acc1);
    #pragma unroll
    for (int off = 16; off; off >>= 1) acc = fminf(acc, __shfl_xor_sync(0xFFFFFFFFu, acc, off));
    if (lane == 0) g_cscore[gw] = acc * di;
}

// ---------------- cluster centers ----------------
__global__ __launch_bounds__(1024)
void k_centers() {
    int b = blockIdx.x;
    __shared__ unsigned long long buf[4096];
    int tid = threadIdx.x;
    for (int i = tid; i < 4096; i += 1024) {
        unsigned long long key = 0ULL;
        if (i < SS) {
            unsigned int bits = __float_as_uint(g_cscore[b*SS + i]);
            key = ((unsigned long long)bits << 32) | (unsigned int)(~(unsigned int)i);
        }
        buf[i] = key;
    }
    __syncthreads();
    bitonic_asc(buf, 4096, tid, 1024);
    for (int k = tid; k < KCL; k += 1024) {
        unsigned long long key = buf[4095 - k];
        g_centers[b*KCL + k] = (int)(~(unsigned int)key);
    }
}

// ---------------- cluster assignment + pixcl + weights (fused) ----------------
__global__ void k_assign() {
    int b = blockIdx.y;
    int s = blockIdx.x * blockDim.x + threadIdx.x;
    __shared__ int cs[KCL];
    for (int t = threadIdx.x; t < KCL; t += blockDim.x) cs[t] = g_centers[b*KCL + t];
    __syncthreads();
    if (s >= SS) return;
    float best = 3.4e38f; int bk = 0, ovr = -1;
    for (int k = 0; k < KCL; k++) {
        int ck = cs[k];
        if (ck == s) ovr = k;
        float d = g_dist[((size_t)b*SS + ck)*SS + s];
        if (d < best) { best = d; bk = k; }
    }
    int cl = (ovr >= 0) ? ovr : bk;
    g_cluster[b*SS + s] = cl;
    g_pixcl[b*HWP + g_topidx[b*SS + s]] = cl;
    atomicAdd(&g_allw[b*KCL + cl], g_conf[b*SS + s]);
}

// ---------------- merge ----------------
__global__ void k_merge() {
    int b = blockIdx.y, s = blockIdx.x, c = threadIdx.x;
    int cl = g_cluster[b*SS + s];
    float nw = g_conf[b*SS + s] / (g_allw[b*KCL + cl] + 1e-6f);
    atomicAdd(&g_merged[((size_t)b*KCL + cl)*CC + c],
              g_tokens[((size_t)b*SSP + s)*CC + c] * nw);
}

// ---------------- fused final write (float4) ----------------
__global__ void k_finalize(const float* __restrict__ x, float* __restrict__ out) {
    size_t q = (size_t)blockIdx.x * blockDim.x + threadIdx.x;   // float4 index
    if (q >= (size_t)NN * CC * HWP / 4) return;
    size_t idx = q * 4;
    int b   = (int)(idx / ((size_t)CC * HWP));
    int rem = (int)(idx % ((size_t)CC * HWP));
    int c   = rem / HWP;
    int p   = rem % HWP;        // p % 4 == 0 (HWP divisible by 4)
    float4 v;
    if (g_isego[b]) v = *(const float4*)(x + idx);
    else {
        const int4 cl4 = *(const int4*)(g_pixcl + b*HWP + p);
        const float* mb = g_merged + (size_t)b*KCL*CC + c;
        v.x = (cl4.x >= 0) ? mb[(size_t)cl4.x*CC] : 0.f;
        v.y = (cl4.y >= 0) ? mb[(size_t)cl4.y*CC] : 0.f;
        v.z = (cl4.z >= 0) ? mb[(size_t)cl4.z*CC] : 0.f;
        v.w = (cl4.w >= 0) ? mb[(size_t)cl4.w*CC] : 0.f;
    }
    *(float4*)(out + idx) = v;
}

// ---------------- launch ----------------
extern "C" void kernel_launch(void* const* d_in, const int* in_sizes, int n_in,
                              void* d_out, int out_size) {
    const float* x   = (const float*)d_in[0];
    const float* w1  = (const float*)d_in[1];
    const float* b1  = (const float*)d_in[2];
    const float* w2  = (const float*)d_in[3];
    const float* b2  = (const float*)d_in[4];
    const float* dis = (const float*)d_in[5];
    const int*   rl  = (const int*)d_in[6];
    int nrec = in_sizes[6];
    float* out = (float*)d_out;

    static int attr_set = 0;
    if (!attr_set) {
        cudaFuncSetAttribute(k_dist_mma, cudaFuncAttributeMaxDynamicSharedMemorySize, DI_SMEM);
        attr_set = 1;
    }

    k_init<<<(NN*KCL*CC/4 + 255)/256, 256>>>(w1, rl, nrec);
    k_score_apx<<<dim3((HWP + 63)/64, NN), 256>>>(x, b1, w2, b2);
    k_thresh_cand<<<NN, 1024>>>(dis);
    k_gx<<<dim3(MAXC, NN), 256>>>(x);
    k_score_exact<<<dim3(MAXC/64, NN), 256>>>(w1, b1, w2, b2, dis);
    k_topk_c<<<NN, 1024>>>();
    k_gather_ln<<<dim3(SS, NN), 256>>>();
    k_dist_mma<<<dim3(NPAIR, NN), 256, DI_SMEM>>>();
    k_knn_merge<<<(NS*32 + 255)/256, 256>>>();
    k_parent<<<(NS*32 + 255)/256, 256>>>();
    k_centers<<<NN, 1024>>>();
    k_assign<<<dim3((SS + 255)/256, NN), 256>>>();
    k_merge<<<dim3(SS, NN), 256>>>();
    k_finalize<<<(unsigned)(((size_t)NN*CC*HWP/4 + 255)/256), 256>>>(x, out);
}

// round 16
// speedup vs baseline: 1.0759x; 1.0759x over previous
#include <cuda_runtime.h>
#include <cuda_fp16.h>
#include <stdint.h>
#include <math.h>

#define NN   8
#define CC   256
#define HH   100
#define WWW  252
#define HWP  (HH*WWW)        // 25200
#define SS   2520
#define SSP  2560            // padded to 20*128
#define KCL  315
#define KNNK 10
#define NS   (NN*SS)
#define MAXC 8192            // max candidates per image
#define MARG 0.006f          // score-domain safety margin for approx pass
#define NTIL (SSP/128)       // 20

// ---------------- scratch ----------------
__device__ int   g_topidx[NS];
__device__ float g_conf[NS];
__device__ float g_tokens[NN*SSP*CC];                // pad rows stay static-zero
__device__ float g_sq[NS];
__device__ float g_dist[NN*SS*SS];                   // 203 MB
__device__ unsigned int g_distmax[NN];
__device__ float g_density[NS];
__device__ float g_noise[NS];
__device__ float g_cscore[NS];
__device__ int   g_centers[NN*KCL];
__device__ int   g_cluster[NS];
__device__ float g_allw[NN*KCL];
__device__ float g_merged[NN*KCL*CC];
__device__ int   g_isego[NN];
__device__ int   g_pixcl[NN*HWP];
__device__ __half g_tspH[2][NN*SSP*CC];              // fp16 2-way split of tokens
__device__ __half g_w1h[CC*CC];                      // fp16 w1 (approx pass)
__device__ float g_sapx[NN*HWP];                     // approx sigmoid
__device__ int   g_ncand[NN];
__device__ int   g_cand[NN*MAXC];
__device__ int   g_cslot[NN*HWP];
__device__ unsigned long long g_ckeys[NN*MAXC];      // compact exact keys
__device__ float g_xc[(size_t)NN*MAXC*CC];           // compact candidate columns
__device__ float g_knnpart[(size_t)NN*SS*NTIL*KNNK]; // per-tile partial 10-smallest (16 MB)

// ---------------- helpers ----------------
__device__ __forceinline__ void mma_f16(float* c, const uint32_t* a, const uint32_t* b) {
    asm volatile("mma.sync.aligned.m16n8k16.row.col.f32.f16.f16.f32 "
        "{%0,%1,%2,%3}, {%4,%5,%6,%7}, {%8,%9}, {%0,%1,%2,%3};"
        : "+f"(c[0]), "+f"(c[1]), "+f"(c[2]), "+f"(c[3])
        : "r"(a[0]), "r"(a[1]), "r"(a[2]), "r"(a[3]), "r"(b[0]), "r"(b[1]));
}
__device__ __forceinline__ uint32_t smem_u32(const void* p) {
    uint32_t a;
    asm("{ .reg .u64 t; cvta.to.shared.u64 t, %1; cvt.u32.u64 %0, t; }" : "=r"(a) : "l"(p));
    return a;
}
__device__ __forceinline__ void cp16(uint32_t saddr, const void* gaddr) {
    asm volatile("cp.async.cg.shared.global [%0], [%1], 16;" :: "r"(saddr), "l"(gaddr));
}
#define CP_COMMIT() asm volatile("cp.async.commit_group;" ::: "memory")
#define CP_WAIT(n)  asm volatile("cp.async.wait_group %0;" :: "n"(n) : "memory")
__device__ __forceinline__ unsigned int rotl32(unsigned int x, int r) {
    return (x << r) | (x >> (32 - r));
}
__device__ __forceinline__ void ins10(float* tp, float d) {
    if (d < tp[KNNK-1]) {
        tp[KNNK-1] = d;
        #pragma unroll
        for (int t = KNNK-1; t > 0; t--)
            if (tp[t] < tp[t-1]) { float m = tp[t-1]; tp[t-1] = tp[t]; tp[t] = m; }
    }
}

// ---------------- mega init kernel (vectorized) ----------------
__global__ void k_init(const float* __restrict__ w1, const int* __restrict__ rl, int nrec) {
    int i = blockIdx.x * blockDim.x + threadIdx.x;   // grid covers NN*KCL*CC/4
    if (i < NN*KCL*CC/4) ((float4*)g_merged)[i] = make_float4(0.f, 0.f, 0.f, 0.f);
    if (i < NN*HWP/4)    ((int4*)g_pixcl)[i] = make_int4(-1, -1, -1, -1);
    if (i < CC*CC/4) {
        float4 v = ((const float4*)w1)[i];
        __half2* dst = (__half2*)(&g_w1h[i*4]);
        dst[0] = __floats2half2_rn(v.x, v.y);
        dst[1] = __floats2half2_rn(v.z, v.w);
    }
    if (i < NN*KCL)    g_allw[i] = 0.f;
    if (i < NN)      { g_distmax[i] = 0u; g_ncand[i] = 0; }
    if (i == 0) {
        for (int t = 0; t < NN; t++) g_isego[t] = 0;
        int s = 0;
        for (int t = 0; t < nrec; t++) { if (s >= 0 && s < NN) g_isego[s] = 1; s += rl[t]; }
    }
    const int half = NS / 2;
    if (i < half) {   // threefry2x32 key=(0,1), counts (i, i+half)
        unsigned int x0 = (unsigned int)i, x1 = (unsigned int)(i + half);
        const unsigned int ks0 = 0u, ks1 = 1u, ks2 = 0x1BD11BDAu ^ 0u ^ 1u;
        x0 += ks0; x1 += ks1;
#define RG4(a0,a1,a2,a3) \
        x0 += x1; x1 = rotl32(x1,a0); x1 ^= x0; \
        x0 += x1; x1 = rotl32(x1,a1); x1 ^= x0; \
        x0 += x1; x1 = rotl32(x1,a2); x1 ^= x0; \
        x0 += x1; x1 = rotl32(x1,a3); x1 ^= x0;
        RG4(13,15,26,6)  x0 += ks1; x1 += ks2 + 1u;
        RG4(17,29,16,24) x0 += ks2; x1 += ks0 + 2u;
        RG4(13,15,26,6)  x0 += ks0; x1 += ks1 + 3u;
        RG4(17,29,16,24) x0 += ks1; x1 += ks2 + 4u;
        RG4(13,15,26,6)  x0 += ks2; x1 += ks0 + 5u;
#undef RG4
        g_noise[i]        = __uint_as_float((x0 >> 9) | 0x3f800000u) - 1.0f;
        g_noise[i + half] = __uint_as_float((x1 >> 9) | 0x3f800000u) - 1.0f;
    }
}

// ================= PASS 1: approx score via fp16 mma =================
#define KC  32
#define KP  40                 // padded smem row stride (halves)
__global__ __launch_bounds__(256)
void k_score_apx(const float* __restrict__ x, const float* __restrict__ b1,
                 const float* __restrict__ w2, const float* __restrict__ b2)
{
    __shared__ char sA[256*KP*2];
    __shared__ char sB[64*KP*2];
    __shared__ float sh_b1[CC], sh_w2[CC];
    __shared__ float red[64];
    int n  = blockIdx.y;
    int p0 = blockIdx.x * 64;
    int tid = threadIdx.x, lane = tid & 31, wid = tid >> 5;
    int g = lane >> 2, tg = lane & 3;
    int wm = wid & 3, wn = wid >> 2;
    const float* xn = x + (size_t)n * CC * HWP;

    if (tid < CC) { sh_b1[tid] = b1[tid]; sh_w2[tid] = w2[tid]; }
    if (tid < 64) red[tid] = 0.f;

    float acc[4][4][4];
    #pragma unroll
    for (int mt = 0; mt < 4; mt++)
        #pragma unroll
        for (int nt = 0; nt < 4; nt++)
            #pragma unroll
            for (int r = 0; r < 4; r++) acc[mt][nt][r] = 0.f;

    for (int c = 0; c < CC/KC; c++) {
        {   // A: w1 fp16 rows
            int d = tid;
            const uint4* src = (const uint4*)(&g_w1h[d*CC + c*KC]);
            uint4* dst = (uint4*)(sA + d*(KP*2));
            dst[0] = src[0]; dst[1] = src[1]; dst[2] = src[2]; dst[3] = src[3];
        }
        {   // B: x fp32 -> fp16 transposed; row-pair loads -> half2 stores
            int kp = tid >> 4;      // 0..15 -> k = 2*kp
            int pq = tid & 15;
            int p  = p0 + pq*4;
            int kg = c*KC + 2*kp;
            const float* r0 = xn + (size_t)kg * HWP + p;
            const float* r1 = r0 + HWP;
            float v0[4], v1[4];
            if (p + 4 <= HWP) {
                float4 a = *(const float4*)r0; v0[0]=a.x; v0[1]=a.y; v0[2]=a.z; v0[3]=a.w;
                float4 bq = *(const float4*)r1; v1[0]=bq.x; v1[1]=bq.y; v1[2]=bq.z; v1[3]=bq.w;
            } else {
                #pragma unroll
                for (int j = 0; j < 4; j++) {
                    v0[j] = (p+j < HWP) ? r0[j] : 0.f;
                    v1[j] = (p+j < HWP) ? r1[j] : 0.f;
                }
            }
            #pragma unroll
            for (int j = 0; j < 4; j++) {
                __half2 h = __floats2half2_rn(v0[j], v1[j]);
                *(__half2*)(sB + (pq*4+j)*(KP*2) + (2*kp)*2) = h;
            }
        }
        __syncthreads();
        #pragma unroll
        for (int ks = 0; ks < 2; ks++) {
            uint32_t af[4][4], bf[4][2];
            const char* Ab = sA + ks*32 + tg*4;
            #pragma unroll
            for (int mt = 0; mt < 4; mt++) {
                const char* pA = Ab + (wm*64 + mt*16 + g)*(KP*2);
                af[mt][0] = *(const uint32_t*)pA;
                af[mt][1] = *(const uint32_t*)(pA + 8*(KP*2));
                af[mt][2] = *(const uint32_t*)(pA + 16);
                af[mt][3] = *(const uint32_t*)(pA + 8*(KP*2) + 16);
            }
            const char* Bb = sB + ks*32 + tg*4;
            #pragma unroll
            for (int nt = 0; nt < 4; nt++) {
                const char* pB = Bb + (wn*32 + nt*8 + g)*(KP*2);
                bf[nt][0] = *(const uint32_t*)pB;
                bf[nt][1] = *(const uint32_t*)(pB + 16);
            }
            #pragma unroll
            for (int mt = 0; mt < 4; mt++)
                #pragma unroll
                for (int nt = 0; nt < 4; nt++)
                    mma_f16(acc[mt][nt], af[mt], bf[nt]);
        }
        __syncthreads();
    }

    float v[4][2];
    #pragma unroll
    for (int nt = 0; nt < 4; nt++) { v[nt][0] = 0.f; v[nt][1] = 0.f; }
    #pragma unroll
    for (int mt = 0; mt < 4; mt++) {
        int d0 = wm*64 + mt*16 + g;
        float hb0 = sh_b1[d0],   hw0 = sh_w2[d0];
        float hb1 = sh_b1[d0+8], hw1 = sh_w2[d0+8];
        #pragma unroll
        for (int nt = 0; nt < 4; nt++) {
            float h;
            h = acc[mt][nt][0] + hb0; v[nt][0] += (h > 0.f ? h : 0.f) * hw0;
            h = acc[mt][nt][1] + hb0; v[nt][1] += (h > 0.f ? h : 0.f) * hw0;
            h = acc[mt][nt][2] + hb1; v[nt][0] += (h > 0.f ? h : 0.f) * hw1;
            h = acc[mt][nt][3] + hb1; v[nt][1] += (h > 0.f ? h : 0.f) * hw1;
        }
    }
    #pragma unroll
    for (int nt = 0; nt < 4; nt++)
        #pragma unroll
        for (int par = 0; par < 2; par++) {
            float s = v[nt][par];
            s += __shfl_xor_sync(0xFFFFFFFFu, s, 4);
            s += __shfl_xor_sync(0xFFFFFFFFu, s, 8);
            s += __shfl_xor_sync(0xFFFFFFFFu, s, 16);
            v[nt][par] = s;
        }
    if (lane < 4) {
        #pragma unroll
        for (int nt = 0; nt < 4; nt++) {
            atomicAdd(&red[wn*32 + nt*8 + lane*2 + 0], v[nt][0]);
            atomicAdd(&red[wn*32 + nt*8 + lane*2 + 1], v[nt][1]);
        }
    }
    __syncthreads();
    if (tid < 64) {
        int p = p0 + tid;
        if (p < HWP) {
            float z = red[tid] + b2[0];
            g_sapx[(size_t)n*HWP + p] = 1.f / (1.f + expf(-z));
        }
    }
}

// ---------------- threshold + PIXEL-ORDERED candidate compaction ----------------
__global__ __launch_bounds__(1024)
void k_thresh_cand(const float* __restrict__ dis) {
    int b = blockIdx.x;
    __shared__ unsigned int hist[8][256], histsum[256];
    __shared__ unsigned int sh_prefix;
    __shared__ int sh_R;
    __shared__ int warpsum[32];
    __shared__ int sh_base;
    int tid = threadIdx.x, lane = tid & 31, wid = tid >> 5;
    int wid8 = wid & 7;
    if (tid == 0) { sh_prefix = 0u; sh_R = SS; sh_base = 0; }
    for (int byte = 3; byte >= 0; byte--) {
        for (int i = tid; i < 8*256; i += 1024) ((unsigned int*)hist)[i] = 0u;
        __syncthreads();
        int shift = byte * 8;
        unsigned int pref = sh_prefix;
        for (int i = tid; i < HWP; i += 1024) {
            float vlo = fmaxf(g_sapx[(size_t)b*HWP + i] - MARG, 0.f) * dis[(size_t)b*HWP + i];
            unsigned int k = __float_as_uint(vlo);
            if (byte == 3 || (k >> (shift+8)) == (pref >> (shift+8)))
                atomicAdd(&hist[wid8][(k >> shift) & 0xFFu], 1u);
        }
        __syncthreads();
        if (tid < 256) {
            unsigned int s = 0;
            #pragma unroll
            for (int w = 0; w < 8; w++) s += hist[w][tid];
            histsum[tid] = s;
        }
        __syncthreads();
        if (tid == 0) {
            int R = sh_R; long long cum = 0; int chosen = 0;
            for (int v = 255; v >= 0; v--) {
                cum += histsum[v];
                if (cum >= R) { chosen = v; sh_R = R - (int)(cum - histsum[v]); break; }
            }
            sh_prefix = pref | ((unsigned int)chosen << shift);
        }
        __syncthreads();
    }
    unsigned int T = sh_prefix;
    // ordered compaction: chunks of 1024 consecutive pixels, ballot + block scan
    for (int base = 0; base < HWP; base += 1024) {
        int p = base + tid;
        bool c = false;
        size_t i = (size_t)b*HWP + p;
        if (p < HWP) {
            float hi = (g_sapx[i] + MARG) * dis[i];
            c = (__float_as_uint(hi) >= T);
        }
        unsigned int bal = __ballot_sync(0xFFFFFFFFu, c);
        int wr = __popc(bal & ((1u << lane) - 1u));
        if (lane == 0) warpsum[wid] = __popc(bal);
        __syncthreads();
        if (tid < 32) {
            int v2 = warpsum[tid];
            #pragma unroll
            for (int off = 1; off < 32; off <<= 1) {
                int u = __shfl_up_sync(0xFFFFFFFFu, v2, off);
                if ((int)tid >= off) v2 += u;
            }
            warpsum[tid] = v2;   // inclusive scan
        }
        __syncthreads();
        int woff = (wid == 0) ? 0 : warpsum[wid - 1];
        if (c) {
            int slot = sh_base + woff + wr;
            if (slot < MAXC) { g_cand[b*MAXC + slot] = p; g_cslot[i] = slot; }
        }
        __syncthreads();
        if (tid == 0) sh_base += warpsum[31];
        __syncthreads();
    }
    if (tid == 0) g_ncand[b] = sh_base;
}

// ---------------- gather candidate columns compact (one block per candidate) ----------------
__global__ void k_gx(const float* __restrict__ x) {
    int b = blockIdx.y, s = blockIdx.x, c = threadIdx.x;
    int nc = min(g_ncand[b], MAXC);
    if (s >= nc) return;
    int pix = g_cand[b*MAXC + s];
    g_xc[((size_t)b*MAXC + s)*CC + c] = x[((size_t)b*CC + c)*HWP + pix];
}

// ================= PASS 2: exact fp32 SIMT score on candidates =================
__global__ __launch_bounds__(256, 2)
void k_score_exact(const float* __restrict__ w1, const float* __restrict__ b1,
                   const float* __restrict__ w2, const float* __restrict__ b2,
                   const float* __restrict__ dis)
{
    int b  = blockIdx.y;
    int c0 = blockIdx.x * 64;
    int nc = min(g_ncand[b], MAXC);
    if (c0 >= nc) return;
    __shared__ float As[KC][CC];
    __shared__ float Bs[KC][64];
    __shared__ float red[16][64];
    __shared__ int   sh_pix[64];
    int tid = threadIdx.x;
    int tx = tid & 15, ty = tid >> 4;
    if (tid < 64) sh_pix[tid] = (c0 + tid < nc) ? g_cand[b*MAXC + c0 + tid] : -1;

    float acc[16][4];
    #pragma unroll
    for (int r = 0; r < 16; r++)
        #pragma unroll
        for (int j = 0; j < 4; j++) acc[r][j] = 0.f;

    for (int k0 = 0; k0 < CC; k0 += KC) {
        for (int t = tid; t < CC * (KC/4); t += 256) {
            int d  = t >> 3, kq = t & 7;
            float4 v = *(const float4*)(w1 + (size_t)d * CC + k0 + kq*4);
            As[kq*4+0][d] = v.x; As[kq*4+1][d] = v.y;
            As[kq*4+2][d] = v.z; As[kq*4+3][d] = v.w;
        }
        {
            int j = tid >> 2, kq2 = (tid & 3) * 2;
            bool ok = (c0 + j < nc);
            #pragma unroll
            for (int q = 0; q < 2; q++) {
                int kq = kq2 + q;
                float4 v = ok ? *(const float4*)(&g_xc[((size_t)b*MAXC + c0 + j)*CC + k0 + kq*4])
                              : make_float4(0.f,0.f,0.f,0.f);
                Bs[kq*4+0][j] = v.x; Bs[kq*4+1][j] = v.y;
                Bs[kq*4+2][j] = v.z; Bs[kq*4+3][j] = v.w;
            }
        }
        __syncthreads();
        #pragma unroll
        for (int kk = 0; kk < KC; kk++) {
            float a[16];
            *(float4*)(a+0)  = *(float4*)&As[kk][ty*16+0];
            *(float4*)(a+4)  = *(float4*)&As[kk][ty*16+4];
            *(float4*)(a+8)  = *(float4*)&As[kk][ty*16+8];
            *(float4*)(a+12) = *(float4*)&As[kk][ty*16+12];
            float4 bf = *(float4*)&Bs[kk][tx*4];
            float bb[4] = {bf.x, bf.y, bf.z, bf.w};
            #pragma unroll
            for (int r = 0; r < 16; r++)
                #pragma unroll
                for (int j = 0; j < 4; j++) acc[r][j] += a[r] * bb[j];
        }
        __syncthreads();
    }
    float part[4] = {0.f, 0.f, 0.f, 0.f};
    #pragma unroll
    for (int r = 0; r < 16; r++) {
        int d = ty*16 + r;
        float bbv = b1[d], wwv = w2[d];
        #pragma unroll
        for (int j = 0; j < 4; j++) {
            float h = acc[r][j] + bbv;
            h = h > 0.f ? h : 0.f;
            part[j] += h * wwv;
        }
    }
    #pragma unroll
    for (int j = 0; j < 4; j++) red[ty][tx*4+j] = part[j];
    __syncthreads();
    if (tid < 64) {
        int pix = sh_pix[tid];
        if (pix >= 0) {
            float s = 0.f;
            #pragma unroll
            for (int r = 0; r < 16; r++) s += red[r][tid];
            float z  = s + b2[0];
            float sc = 1.f / (1.f + expf(-z));
            sc *= dis[(size_t)b*HWP + pix];
            unsigned int bits = __float_as_uint(sc);
            g_ckeys[b*MAXC + c0 + tid] =
                ((unsigned long long)bits << 32) | (unsigned int)(~(unsigned int)pix);
        }
    }
}

// ---------------- bitonic ascending sort ----------------
__device__ __forceinline__ void bitonic_asc(unsigned long long* buf, int n, int tid, int nth) {
    for (int k2 = 2; k2 <= n; k2 <<= 1)
        for (int j = k2 >> 1; j > 0; j >>= 1) {
            __syncthreads();
            for (int i = tid; i < n; i += nth) {
                int ixj = i ^ j;
                if (ixj > i) {
                    unsigned long long a = buf[i], b = buf[ixj];
                    bool up = ((i & k2) == 0);
                    if (up ? (a > b) : (a < b)) { buf[i] = b; buf[ixj] = a; }
                }
            }
        }
    __syncthreads();
}

// ---------------- exact top-S over compact candidate keys ----------------
__global__ __launch_bounds__(1024)
void k_topk_c() {
    int b = blockIdx.x;
    int nc = min(g_ncand[b], MAXC);
    const unsigned long long* keys = g_ckeys + (size_t)b * MAXC;
    __shared__ unsigned int hist[8][256], histsum[256];
    __shared__ unsigned long long sh_prefix;
    __shared__ int sh_R, sh_cnt;
    __shared__ unsigned long long buf[4096];
    int tid = threadIdx.x, wid8 = (tid >> 5) & 7;
    if (tid == 0) { sh_prefix = 0ULL; sh_R = SS; sh_cnt = 0; }

    for (int byte = 7; byte >= 0; byte--) {
        for (int i = tid; i < 8*256; i += 1024) ((unsigned int*)hist)[i] = 0u;
        __syncthreads();
        int shift = byte * 8;
        unsigned long long pref = sh_prefix;
        for (int i = tid; i < nc; i += 1024) {
            unsigned long long k = keys[i];
            if (byte == 7 || (k >> (shift+8)) == (pref >> (shift+8)))
                atomicAdd(&hist[wid8][(unsigned)(k >> shift) & 0xFFu], 1u);
        }
        __syncthreads();
        if (tid < 256) {
            unsigned int s = 0;
            #pragma unroll
            for (int w = 0; w < 8; w++) s += hist[w][tid];
            histsum[tid] = s;
        }
        __syncthreads();
        if (tid == 0) {
            int R = sh_R; long long cum = 0; int chosen = 0;
            for (int v = 255; v >= 0; v--) {
                cum += histsum[v];
                if (cum >= R) { chosen = v; sh_R = R - (int)(cum - histsum[v]); break; }
            }
            sh_prefix = pref | ((unsigned long long)chosen << shift);
        }
        __syncthreads();
    }
    unsigned long long T = sh_prefix;
    for (int i = tid; i < 4096; i += 1024) buf[i] = 0ULL;
    __syncthreads();
    for (int i = tid; i < nc; i += 1024) {
        unsigned long long k = keys[i];
        if (k >= T) { int pos = atomicAdd(&sh_cnt, 1); if (pos < 4096) buf[pos] = k; }
    }
    __syncthreads();
    bitonic_asc(buf, 4096, tid, 1024);
    for (int s = tid; s < SS; s += 1024) {
        unsigned long long k = buf[4095 - s];
        g_topidx[b*SS + s] = (int)(~(unsigned int)k);
        g_conf  [b*SS + s] = __uint_as_float((unsigned int)(k >> 32));
    }
}

// ---------------- gather (compact) + layernorm + *conf + fp16x2 split + sumsq ----------------
__global__ void k_gather_ln() {
    int b = blockIdx.y, s = blockIdx.x;
    int c = threadIdx.x;
    __shared__ float sh[256];
    int   pix  = g_topidx[b*SS + s];
    float conf = g_conf[b*SS + s];
    int   slot = g_cslot[b*HWP + pix];
    float v = g_xc[((size_t)b*MAXC + slot)*CC + c];

    sh[c] = v; __syncthreads();
    for (int st = 128; st > 0; st >>= 1) { if (c < st) sh[c] += sh[c+st]; __syncthreads(); }
    float mu = sh[0] * (1.f/256.f);
    __syncthreads();
    float dv = v - mu;
    sh[c] = dv * dv; __syncthreads();
    for (int st = 128; st > 0; st >>= 1) { if (c < st) sh[c] += sh[c+st]; __syncthreads(); }
    float var = sh[0] * (1.f/256.f);
    __syncthreads();
    float t = dv / sqrtf(var + 1e-5f) * conf;
    size_t o = ((size_t)b*SSP + s)*CC + c;
    g_tokens[o] = t;
    __half t1 = __float2half(t);
    __half t2 = __float2half(t - __half2float(t1));
    g_tspH[0][o] = t1; g_tspH[1][o] = t2;
    sh[c] = t * t; __syncthreads();
    for (int st = 128; st > 0; st >>= 1) { if (c < st) sh[c] += sh[c+st]; __syncthreads(); }
    if (c == 0) g_sq[b*SS + s] = sh[0];
}

// ================= distance GEMM: fp16x2 (3 terms), cp.async, fused partial-KNN =================
#define DI_T  (128*KP*2)             // 10240 B per split tile
#define DI_STG (4*DI_T)              // 40960 per stage
#define DI_SMEM (2*DI_STG)           // 81920 (Dt 66048 + sm_part 10240 fit)
#define NPAIR (NTIL*(NTIL+1)/2)      // 210

__global__ __launch_bounds__(256, 2)
void k_dist_mma() {
    int b = blockIdx.y;
    int t = blockIdx.x;
    int bi = (int)((sqrtf(8.f*t + 1.f) - 1.f) * 0.5f);
    while ((bi+1)*(bi+2)/2 <= t) bi++;
    while (bi*(bi+1)/2 > t) bi--;
    int bj = t - bi*(bi+1)/2;
    extern __shared__ char smp[];
    __shared__ float s_sqi[128], s_sqj[128], wmaxs[8];
    int tid = threadIdx.x, lane = tid & 31, wid = tid >> 5;
    int g = lane >> 2, tg = lane & 3;
    int wm = wid & 1, wn = wid >> 1;
    int i0 = bi * 128, j0 = bj * 128;
    uint32_t sbase = smem_u32(smp);

    if (tid < 128)      s_sqi[tid]     = (i0 + tid     < SS) ? g_sq[b*SS + i0 + tid]     : 0.f;
    else                s_sqj[tid-128] = (j0 + tid-128 < SS) ? g_sq[b*SS + j0 + tid-128] : 0.f;

    int r = tid & 127, side = tid >> 7;
    int grow = (side ? j0 : i0) + r;
    #pragma unroll
    for (int s = 0; s < 2; s++) {
        const char* src = (const char*)(&g_tspH[s][((size_t)(b*SSP + grow))*CC]);
        uint32_t dst = sbase + (side*2 + s)*DI_T + r*(KP*2);
        #pragma unroll
        for (int q = 0; q < 4; q++) cp16(dst + q*16, src + q*16);
    }
    CP_COMMIT();

    float acc[4][4][4];
    #pragma unroll
    for (int mt = 0; mt < 4; mt++)
        #pragma unroll
        for (int nt = 0; nt < 4; nt++)
            #pragma unroll
            for (int rr = 0; rr < 4; rr++) acc[mt][nt][rr] = 0.f;

    const int TA[3] = {0,0,1};
    const int TB[3] = {0,1,0};

    for (int c = 0; c < CC/KC; c++) {
        int stg = c & 1;
        if (c + 1 < CC/KC) {
            int nstg = stg ^ 1;
            #pragma unroll
            for (int s = 0; s < 2; s++) {
                const char* src = (const char*)(&g_tspH[s][((size_t)(b*SSP + grow))*CC + (c+1)*KC]);
                uint32_t dst = sbase + nstg*DI_STG + (side*2 + s)*DI_T + r*(KP*2);
                #pragma unroll
                for (int q = 0; q < 4; q++) cp16(dst + q*16, src + q*16);
            }
            CP_COMMIT();
            CP_WAIT(1);
        } else {
            CP_WAIT(0);
        }
        __syncthreads();
        const char* base = smp + stg*DI_STG;
        #pragma unroll
        for (int term = 0; term < 3; term++) {
            int sa = TA[term], sb = TB[term];
            #pragma unroll
            for (int ks = 0; ks < 2; ks++) {
                uint32_t af[4][4], bf[4][2];
                const char* Ab = base + sa*DI_T + ks*32 + tg*4;
                #pragma unroll
                for (int mt = 0; mt < 4; mt++) {
                    const char* pA = Ab + (wm*64 + mt*16 + g)*(KP*2);
                    af[mt][0] = *(const uint32_t*)pA;
                    af[mt][1] = *(const uint32_t*)(pA + 8*(KP*2));
                    af[mt][2] = *(const uint32_t*)(pA + 16);
                    af[mt][3] = *(const uint32_t*)(pA + 8*(KP*2) + 16);
                }
                const char* Bb = base + (2 + sb)*DI_T + ks*32 + tg*4;
                #pragma unroll
                for (int nt = 0; nt < 4; nt++) {
                    const char* pB = Bb + (wn*32 + nt*8 + g)*(KP*2);
                    bf[nt][0] = *(const uint32_t*)pB;
                    bf[nt][1] = *(const uint32_t*)(pB + 16);
                }
                #pragma unroll
                for (int mt = 0; mt < 4; mt++)
                    #pragma unroll
                    for (int nt = 0; nt < 4; nt++)
                        mma_f16(acc[mt][nt], af[mt], bf[nt]);
            }
        }
        __syncthreads();
    }

    float* Dt = (float*)smp;   // [128][129] = 66048 B
    float* sm_part = (float*)(smp + 66048);  // [256][10] = 10240 B
    float tmax = 0.f;
    #pragma unroll
    for (int mt = 0; mt < 4; mt++) {
        #pragma unroll
        for (int nt = 0; nt < 4; nt++) {
            int il0 = wm*64 + mt*16 + g;
            int jl0 = wn*32 + nt*8 + tg*2;
            #pragma unroll
            for (int rr = 0; rr < 4; rr++) {
                int il = il0 + ((rr >> 1) ? 8 : 0);
                int jl = jl0 + (rr & 1);
                float d2 = s_sqi[il] + s_sqj[jl] - 2.f * acc[mt][nt][rr];
                float d  = sqrtf(fmaxf(d2, 1e-12f)) * 0.0625f;
                Dt[il*129 + jl] = d;
                if (i0 + il < SS && j0 + jl < SS) tmax = fmaxf(tmax, d);
            }
        }
    }
    __syncthreads();
    for (int idx = tid; idx < 128*128; idx += 256) {
        int il = idx >> 7, jj = idx & 127;
        int i = i0 + il, j = j0 + jj;
        if (i < SS && j < SS) g_dist[((size_t)b*SS + i)*SS + j] = Dt[il*129 + jj];
    }
    if (bi != bj) {
        for (int idx = tid; idx < 128*128; idx += 256) {
            int jl = idx >> 7, ii = idx & 127;
            int i = i0 + ii, j = j0 + jl;
            if (i < SS) g_dist[((size_t)b*SS + j)*SS + i] = Dt[ii*129 + jl];
        }
    }

    // ---- fused partial top-10: i-side rows, tile column bj ----
    {
        int row = tid >> 1, half = tid & 1;
        float tp[KNNK];
        #pragma unroll
        for (int q = 0; q < KNNK; q++) tp[q] = 3.4e38f;
        if (i0 + row < SS) {
            const float* drow = Dt + row*129 + half*64;
            for (int jj = 0; jj < 64; jj++) {
                int jl = half*64 + jj;
                float d = (j0 + jl < SS) ? drow[jj] : 3.4e38f;
                ins10(tp, d);
            }
        }
        #pragma unroll
        for (int q = 0; q < KNNK; q++) sm_part[tid*KNNK + q] = tp[q];
        __syncwarp();
        if (half == 0 && i0 + row < SS) {
            const float* a  = &sm_part[tid*KNNK];
            const float* bq = &sm_part[(tid+1)*KNNK];
            float* dst = &g_knnpart[(((size_t)b*SS + i0 + row)*NTIL + bj)*KNNK];
            int ia = 0, ib = 0;
            #pragma unroll
            for (int q = 0; q < KNNK; q++) {
                float va = a[ia], vb = bq[ib];
                if (va <= vb) { dst[q] = va; ia++; } else { dst[q] = vb; ib++; }
            }
        }
    }
    // ---- mirror side: j-rows, tile column bi (only off-diagonal) ----
    if (bi != bj) {
        __syncthreads();
        int row = tid >> 1, half = tid & 1;   // row = jl ; j always < SS (bj <= 18)
        float tp[KNNK];
        #pragma unroll
        for (int q = 0; q < KNNK; q++) tp[q] = 3.4e38f;
        for (int ii = 0; ii < 64; ii++) {
            int il = half*64 + ii;
            float d = (i0 + il < SS) ? Dt[il*129 + row] : 3.4e38f;
            ins10(tp, d);
        }
        #pragma unroll
        for (int q = 0; q < KNNK; q++) sm_part[tid*KNNK + q] = tp[q];
        __syncwarp();
        if (half == 0) {
            const float* a  = &sm_part[tid*KNNK];
            const float* bq = &sm_part[(tid+1)*KNNK];
            float* dst = &g_knnpart[(((size_t)b*SS + j0 + row)*NTIL + bi)*KNNK];
            int ia = 0, ib = 0;
            #pragma unroll
            for (int q = 0; q < KNNK; q++) {
                float va = a[ia], vb = bq[ib];
                if (va <= vb) { dst[q] = va; ia++; } else { dst[q] = vb; ib++; }
            }
        }
    }

    #pragma unroll
    for (int off = 16; off; off >>= 1) tmax = fmaxf(tmax, __shfl_xor_sync(0xFFFFFFFFu, tmax, off));
    if (lane == 0) wmaxs[wid] = tmax;
    __syncthreads();
    if (tid == 0) {
        float m = 0.f;
        #pragma unroll
        for (int w = 0; w < 8; w++) m = fmaxf(m, wmaxs[w]);
        atomicMax(&g_distmax[b], __float_as_uint(m));
    }
}

// ---------------- KNN density: merge per-tile partials (16 MB read) ----------------
__global__ void k_knn_merge() {
    int gw = (blockIdx.x * blockDim.x + threadIdx.x) >> 5;
    int lane = threadIdx.x & 31;
    if (gw >= NS) return;
    const float* part = g_knnpart + (size_t)gw * (NTIL*KNNK);
    float top[KNNK];
    #pragma unroll
    for (int t = 0; t < KNNK; t++) top[t] = 3.4e38f;
    for (int idx = lane; idx < NTIL*KNNK; idx += 32) {
        float d = part[idx];
        ins10(top, d);
    }
    int ptr = 0;
    float sumsq = 0.f;
    for (int t = 0; t < KNNK; t++) {
        float cand = (ptr < KNNK) ? top[ptr] : 3.4e38f;
        float m = cand;
        #pragma unroll
        for (int off = 16; off; off >>= 1) m = fminf(m, __shfl_xor_sync(0xFFFFFFFFu, m, off));
        sumsq += m * m;
        unsigned bal = __ballot_sync(0xFFFFFFFFu, cand == m);
        int src = __ffs(bal) - 1;
        if (lane == src) ptr++;
    }
    if (lane == 0)
        g_density[gw] = expf(-(sumsq * (1.f/KNNK))) + g_noise[gw] * 1e-6f;
}

// ---------------- parent distance + cscore (warp per row, float4, 2-way ILP) ----------------
__global__ void k_parent() {
    int gw = (blockIdx.x * blockDim.x + threadIdx.x) >> 5;
    int lane = threadIdx.x & 31;
    if (gw >= NS) return;
    int b = gw / SS, i = gw % SS;
    float di   = g_density[gw];
    float dmax = __uint_as_float(g_distmax[b]);
    const float4* row4  = (const float4*)(g_dist + ((size_t)b*SS + i)*SS);
    const float4* dens4 = (const float4*)(g_density + b*SS);
    float acc0 = dmax, acc1 = dmax;
    int j4 = lane;
    for (; j4 + 32 < SS/4; j4 += 64) {
        float4 dv0 = dens4[j4],      rv0 = row4[j4];
        float4 dv1 = dens4[j4 + 32], rv1 = row4[j4 + 32];
        if (dv0.x > di) acc0 = fminf(acc0, rv0.x);
        if (dv0.y > di) acc0 = fminf(acc0, rv0.y);
        if (dv0.z > di) acc0 = fminf(acc0, rv0.z);
        if (dv0.w > di) acc0 = fminf(acc0, rv0.w);
        if (dv1.x > di) acc1 = fminf(acc1, rv1.x);
        if (dv1.y > di) acc1 = fminf(acc1, rv1.y);
        if (dv1.z > di) acc1 = fminf(acc1, rv1.z);
        if (dv1.w > di) acc1 = fminf(acc1, rv1.w);
    }
    if (j4 < SS/4) {
        float4 dv = dens4[j4], rv = row4[j4];
        if (dv.x > di) acc0 = fminf(acc0, rv.x);
        if (dv.y > di) acc0 = fminf(acc0, rv.y);
        if (dv.z > di) acc0 = fminf(acc0, rv.z);
        if (dv.w > di) acc0 = fminf(acc0, rv.w);
    }
    float acc = fminf(acc0, acc1);
    #pragma unroll
    for (int off = 16; off; off >>= 1) acc = fminf(acc, __shfl_xor_sync(0xFFFFFFFFu, acc, off));
    if (lane == 0) g_cscore[gw] = acc * di;
}

// ---------------- cluster centers ----------------
__global__ __launch_bounds__(1024)
void k_centers() {
    int b = blockIdx.x;
    __shared__ unsigned long long buf[4096];
    int tid = threadIdx.x;
    for (int i = tid; i < 4096; i += 1024) {
        unsigned long long key = 0ULL;
        if (i < SS) {
            unsigned int bits = __float_as_uint(g_cscore[b*SS + i]);
            key = ((unsigned long long)bits << 32) | (unsigned int)(~(unsigned int)i);
        }
        buf[i] = key;
    }
    __syncthreads();
    bitonic_asc(buf, 4096, tid, 1024);
    for (int k = tid; k < KCL; k += 1024) {
        unsigned long long key = buf[4095 - k];
        g_centers[b*KCL + k] = (int)(~(unsigned int)key);
    }
}

// ---------------- cluster assignment + pixcl + weights (fused) ----------------
__global__ void k_assign() {
    int b = blockIdx.y;
    int s = blockIdx.x * blockDim.x + threadIdx.x;
    __shared__ int cs[KCL];
    for (int t = threadIdx.x; t < KCL; t += blockDim.x) cs[t] = g_centers[b*KCL + t];
    __syncthreads();
    if (s >= SS) return;
    float best = 3.4e38f; int bk = 0, ovr = -1;
    for (int k = 0; k < KCL; k++) {
        int ck = cs[k];
        if (ck == s) ovr = k;
        float d = g_dist[((size_t)b*SS + ck)*SS + s];
        if (d < best) { best = d; bk = k; }
    }
    int cl = (ovr >= 0) ? ovr : bk;
    g_cluster[b*SS + s] = cl;
    g_pixcl[b*HWP + g_topidx[b*SS + s]] = cl;
    atomicAdd(&g_allw[b*KCL + cl], g_conf[b*SS + s]);
}

// ---------------- merge ----------------
__global__ void k_merge() {
    int b = blockIdx.y, s = blockIdx.x, c = threadIdx.x;
    int cl = g_cluster[b*SS + s];
    float nw = g_conf[b*SS + s] / (g_allw[b*KCL + cl] + 1e-6f);
    atomicAdd(&g_merged[((size_t)b*KCL + cl)*CC + c],
              g_tokens[((size_t)b*SSP + s)*CC + c] * nw);
}

// ---------------- fused final write (float4) ----------------
__global__ void k_finalize(const float* __restrict__ x, float* __restrict__ out) {
    size_t q = (size_t)blockIdx.x * blockDim.x + threadIdx.x;   // float4 index
    if (q >= (size_t)NN * CC * HWP / 4) return;
    size_t idx = q * 4;
    int b   = (int)(idx / ((size_t)CC * HWP));
    int rem = (int)(idx % ((size_t)CC * HWP));
    int c   = rem / HWP;
    int p   = rem % HWP;        // p % 4 == 0 (HWP divisible by 4)
    float4 v;
    if (g_isego[b]) v = *(const float4*)(x + idx);
    else {
        const int4 cl4 = *(const int4*)(g_pixcl + b*HWP + p);
        const float* mb = g_merged + (size_t)b*KCL*CC + c;
        v.x = (cl4.x >= 0) ? mb[(size_t)cl4.x*CC] : 0.f;
        v.y = (cl4.y >= 0) ? mb[(size_t)cl4.y*CC] : 0.f;
        v.z = (cl4.z >= 0) ? mb[(size_t)cl4.z*CC] : 0.f;
        v.w = (cl4.w >= 0) ? mb[(size_t)cl4.w*CC] : 0.f;
    }
    *(float4*)(out + idx) = v;
}

// ---------------- launch ----------------
extern "C" void kernel_launch(void* const* d_in, const int* in_sizes, int n_in,
                              void* d_out, int out_size) {
    const float* x   = (const float*)d_in[0];
    const float* w1  = (const float*)d_in[1];
    const float* b1  = (const float*)d_in[2];
    const float* w2  = (const float*)d_in[3];
    const float* b2  = (const float*)d_in[4];
    const float* dis = (const float*)d_in[5];
    const int*   rl  = (const int*)d_in[6];
    int nrec = in_sizes[6];
    float* out = (float*)d_out;

    static int attr_set = 0;
    if (!attr_set) {
        cudaFuncSetAttribute(k_dist_mma, cudaFuncAttributeMaxDynamicSharedMemorySize, DI_SMEM);
        attr_set = 1;
    }

    k_init<<<(NN*KCL*CC/4 + 255)/256, 256>>>(w1, rl, nrec);
    k_score_apx<<<dim3((HWP + 63)/64, NN), 256>>>(x, b1, w2, b2);
    k_thresh_cand<<<NN, 1024>>>(dis);
    k_gx<<<dim3(MAXC, NN), 256>>>(x);
    k_score_exact<<<dim3(MAXC/64, NN), 256>>>(w1, b1, w2, b2, dis);
    k_topk_c<<<NN, 1024>>>();
    k_gather_ln<<<dim3(SS, NN), 256>>>();
    k_dist_mma<<<dim3(NPAIR, NN), 256, DI_SMEM>>>();
    k_knn_merge<<<(NS*32 + 255)/256, 256>>>();
    k_parent<<<(NS*32 + 255)/256, 256>>>();
    k_centers<<<NN, 1024>>>();
    k_assign<<<dim3((SS + 255)/256, NN), 256>>>();
    k_merge<<<dim3(SS, NN), 256>>>();
    k_finalize<<<(unsigned)(((size_t)NN*CC*HWP/4 + 255)/256), 256>>>(x, out);
}

// round 17
// speedup vs baseline: 1.0866x; 1.0099x over previous
#include <cuda_runtime.h>
#include <cuda_fp16.h>
#include <stdint.h>
#include <math.h>

#define NN   8
#define CC   256
#define HH   100
#define WWW  252
#define HWP  (HH*WWW)        // 25200
#define SS   2520
#define SSP  2560            // padded to 20*128
#define KCL  315
#define KNNK 10
#define NS   (NN*SS)
#define MAXC 8192            // max candidates per image
#define MARG 0.006f          // score-domain safety margin for approx pass
#define NTIL (SSP/128)       // 20

// ---------------- scratch ----------------
__device__ int   g_topidx[NS];
__device__ float g_conf[NS];
__device__ float g_tokens[NN*SSP*CC];                // pad rows stay static-zero
__device__ float g_sq[NS];
__device__ float g_dist[NN*SS*SS];                   // 203 MB
__device__ unsigned int g_distmax[NN];
__device__ float g_density[NS];
__device__ float g_noise[NS];
__device__ float g_cscore[NS];
__device__ int   g_centers[NN*KCL];
__device__ int   g_cluster[NS];
__device__ float g_allw[NN*KCL];
__device__ float g_merged[NN*KCL*CC];
__device__ int   g_isego[NN];
__device__ int   g_pixcl[NN*HWP];
__device__ __half g_tspH[2][NN*SSP*CC];              // fp16 2-way split of tokens
__device__ __half g_w1h[CC*CC];                      // fp16 w1 (approx pass)
__device__ float g_sapx[NN*HWP];                     // approx sigmoid
__device__ int   g_ncand[NN];
__device__ int   g_cand[NN*MAXC];
__device__ int   g_cslot[NN*HWP];
__device__ unsigned long long g_ckeys[NN*MAXC];      // compact exact keys
__device__ float g_xc[(size_t)NN*MAXC*CC];           // compact candidate columns
__device__ float g_knnpart[(size_t)NN*SS*NTIL*KNNK]; // per-tile partial 10-smallest (16 MB)

// ---------------- helpers ----------------
__device__ __forceinline__ void mma_f16(float* c, const uint32_t* a, const uint32_t* b) {
    asm volatile("mma.sync.aligned.m16n8k16.row.col.f32.f16.f16.f32 "
        "{%0,%1,%2,%3}, {%4,%5,%6,%7}, {%8,%9}, {%0,%1,%2,%3};"
        : "+f"(c[0]), "+f"(c[1]), "+f"(c[2]), "+f"(c[3])
        : "r"(a[0]), "r"(a[1]), "r"(a[2]), "r"(a[3]), "r"(b[0]), "r"(b[1]));
}
__device__ __forceinline__ uint32_t smem_u32(const void* p) {
    uint32_t a;
    asm("{ .reg .u64 t; cvta.to.shared.u64 t, %1; cvt.u32.u64 %0, t; }" : "=r"(a) : "l"(p));
    return a;
}
__device__ __forceinline__ void cp16(uint32_t saddr, const void* gaddr) {
    asm volatile("cp.async.cg.shared.global [%0], [%1], 16;" :: "r"(saddr), "l"(gaddr));
}
#define CP_COMMIT() asm volatile("cp.async.commit_group;" ::: "memory")
#define CP_WAIT(n)  asm volatile("cp.async.wait_group %0;" :: "n"(n) : "memory")
__device__ __forceinline__ unsigned int rotl32(unsigned int x, int r) {
    return (x << r) | (x >> (32 - r));
}
__device__ __forceinline__ void ins10(float* tp, float d) {
    if (d < tp[KNNK-1]) {
        tp[KNNK-1] = d;
        #pragma unroll
        for (int t = KNNK-1; t > 0; t--)
            if (tp[t] < tp[t-1]) { float m = tp[t-1]; tp[t-1] = tp[t]; tp[t] = m; }
    }
}

// ---------------- mega init kernel (vectorized) ----------------
__global__ void k_init(const float* __restrict__ w1, const int* __restrict__ rl, int nrec) {
    int i = blockIdx.x * blockDim.x + threadIdx.x;   // grid covers NN*KCL*CC/4
    if (i < NN*KCL*CC/4) ((float4*)g_merged)[i] = make_float4(0.f, 0.f, 0.f, 0.f);
    if (i < NN*HWP/4)    ((int4*)g_pixcl)[i] = make_int4(-1, -1, -1, -1);
    if (i < CC*CC/4) {
        float4 v = ((const float4*)w1)[i];
        __half2* dst = (__half2*)(&g_w1h[i*4]);
        dst[0] = __floats2half2_rn(v.x, v.y);
        dst[1] = __floats2half2_rn(v.z, v.w);
    }
    if (i < NN*KCL)    g_allw[i] = 0.f;
    if (i < NN)      { g_distmax[i] = 0u; g_ncand[i] = 0; }
    if (i == 0) {
        for (int t = 0; t < NN; t++) g_isego[t] = 0;
        int s = 0;
        for (int t = 0; t < nrec; t++) { if (s >= 0 && s < NN) g_isego[s] = 1; s += rl[t]; }
    }
    const int half = NS / 2;
    if (i < half) {   // threefry2x32 key=(0,1), counts (i, i+half)
        unsigned int x0 = (unsigned int)i, x1 = (unsigned int)(i + half);
        const unsigned int ks0 = 0u, ks1 = 1u, ks2 = 0x1BD11BDAu ^ 0u ^ 1u;
        x0 += ks0; x1 += ks1;
#define RG4(a0,a1,a2,a3) \
        x0 += x1; x1 = rotl32(x1,a0); x1 ^= x0; \
        x0 += x1; x1 = rotl32(x1,a1); x1 ^= x0; \
        x0 += x1; x1 = rotl32(x1,a2); x1 ^= x0; \
        x0 += x1; x1 = rotl32(x1,a3); x1 ^= x0;
        RG4(13,15,26,6)  x0 += ks1; x1 += ks2 + 1u;
        RG4(17,29,16,24) x0 += ks2; x1 += ks0 + 2u;
        RG4(13,15,26,6)  x0 += ks0; x1 += ks1 + 3u;
        RG4(17,29,16,24) x0 += ks1; x1 += ks2 + 4u;
        RG4(13,15,26,6)  x0 += ks2; x1 += ks0 + 5u;
#undef RG4
        g_noise[i]        = __uint_as_float((x0 >> 9) | 0x3f800000u) - 1.0f;
        g_noise[i + half] = __uint_as_float((x1 >> 9) | 0x3f800000u) - 1.0f;
    }
}

// ================= PASS 1: approx score via fp16 mma (register-prefetch pipeline) =================
#define KC  32
#define KP  40                 // padded smem row stride (halves)
__global__ __launch_bounds__(256, 2)
void k_score_apx(const float* __restrict__ x, const float* __restrict__ b1,
                 const float* __restrict__ w2, const float* __restrict__ b2)
{
    __shared__ char sA[256*KP*2];
    __shared__ char sB[64*KP*2];
    __shared__ float sh_b1[CC], sh_w2[CC];
    __shared__ float red[64];
    int n  = blockIdx.y;
    int p0 = blockIdx.x * 64;
    int tid = threadIdx.x, lane = tid & 31, wid = tid >> 5;
    int g = lane >> 2, tg = lane & 3;
    int wm = wid & 3, wn = wid >> 2;
    const float* xn = x + (size_t)n * CC * HWP;

    if (tid < CC) { sh_b1[tid] = b1[tid]; sh_w2[tid] = w2[tid]; }
    if (tid < 64) red[tid] = 0.f;

    int kp = tid >> 4;      // 0..15 -> k = 2*kp
    int pq = tid & 15;
    int p  = p0 + pq*4;
    bool inb = (p + 4 <= HWP);

    float acc[4][4][4];
    #pragma unroll
    for (int mt = 0; mt < 4; mt++)
        #pragma unroll
        for (int nt = 0; nt < 4; nt++)
            #pragma unroll
            for (int r = 0; r < 4; r++) acc[mt][nt][r] = 0.f;

    // prefetch chunk 0
    uint4 pA0, pA1, pA2, pA3;
    float4 pB0, pB1;
    {
        const uint4* srcA = (const uint4*)(&g_w1h[tid*CC]);
        pA0 = srcA[0]; pA1 = srcA[1]; pA2 = srcA[2]; pA3 = srcA[3];
        const float* r0 = xn + (size_t)(2*kp) * HWP + p;
        const float* r1 = r0 + HWP;
        if (inb) { pB0 = *(const float4*)r0; pB1 = *(const float4*)r1; }
        else {
            float t0[4], t1v[4];
            #pragma unroll
            for (int j = 0; j < 4; j++) {
                t0[j] = (p+j < HWP) ? r0[j] : 0.f;
                t1v[j] = (p+j < HWP) ? r1[j] : 0.f;
            }
            pB0 = make_float4(t0[0], t0[1], t0[2], t0[3]);
            pB1 = make_float4(t1v[0], t1v[1], t1v[2], t1v[3]);
        }
    }

    for (int c = 0; c < CC/KC; c++) {
        {   // store prefetched A
            uint4* dst = (uint4*)(sA + tid*(KP*2));
            dst[0] = pA0; dst[1] = pA1; dst[2] = pA2; dst[3] = pA3;
        }
        {   // convert + store prefetched B
            float v0[4] = {pB0.x, pB0.y, pB0.z, pB0.w};
            float v1[4] = {pB1.x, pB1.y, pB1.z, pB1.w};
            #pragma unroll
            for (int j = 0; j < 4; j++) {
                __half2 h = __floats2half2_rn(v0[j], v1[j]);
                *(__half2*)(sB + (pq*4+j)*(KP*2) + (2*kp)*2) = h;
            }
        }
        __syncthreads();
        if (c + 1 < CC/KC) {   // prefetch next chunk (overlaps mma phase)
            const uint4* srcA = (const uint4*)(&g_w1h[tid*CC + (c+1)*KC]);
            pA0 = srcA[0]; pA1 = srcA[1]; pA2 = srcA[2]; pA3 = srcA[3];
            const float* r0 = xn + (size_t)((c+1)*KC + 2*kp) * HWP + p;
            const float* r1 = r0 + HWP;
            if (inb) { pB0 = *(const float4*)r0; pB1 = *(const float4*)r1; }
            else {
                float t0[4], t1v[4];
                #pragma unroll
                for (int j = 0; j < 4; j++) {
                    t0[j] = (p+j < HWP) ? r0[j] : 0.f;
                    t1v[j] = (p+j < HWP) ? r1[j] : 0.f;
                }
                pB0 = make_float4(t0[0], t0[1], t0[2], t0[3]);
                pB1 = make_float4(t1v[0], t1v[1], t1v[2], t1v[3]);
            }
        }
        #pragma unroll
        for (int ks = 0; ks < 2; ks++) {
            uint32_t af[4][4], bf[4][2];
            const char* Ab = sA + ks*32 + tg*4;
            #pragma unroll
            for (int mt = 0; mt < 4; mt++) {
                const char* pA = Ab + (wm*64 + mt*16 + g)*(KP*2);
                af[mt][0] = *(const uint32_t*)pA;
                af[mt][1] = *(const uint32_t*)(pA + 8*(KP*2));
                af[mt][2] = *(const uint32_t*)(pA + 16);
                af[mt][3] = *(const uint32_t*)(pA + 8*(KP*2) + 16);
            }
            const char* Bb = sB + ks*32 + tg*4;
            #pragma unroll
            for (int nt = 0; nt < 4; nt++) {
                const char* pB = Bb + (wn*32 + nt*8 + g)*(KP*2);
                bf[nt][0] = *(const uint32_t*)pB;
                bf[nt][1] = *(const uint32_t*)(pB + 16);
            }
            #pragma unroll
            for (int mt = 0; mt < 4; mt++)
                #pragma unroll
                for (int nt = 0; nt < 4; nt++)
                    mma_f16(acc[mt][nt], af[mt], bf[nt]);
        }
        __syncthreads();
    }

    float v[4][2];
    #pragma unroll
    for (int nt = 0; nt < 4; nt++) { v[nt][0] = 0.f; v[nt][1] = 0.f; }
    #pragma unroll
    for (int mt = 0; mt < 4; mt++) {
        int d0 = wm*64 + mt*16 + g;
        float hb0 = sh_b1[d0],   hw0 = sh_w2[d0];
        float hb1 = sh_b1[d0+8], hw1 = sh_w2[d0+8];
        #pragma unroll
        for (int nt = 0; nt < 4; nt++) {
            float h;
            h = acc[mt][nt][0] + hb0; v[nt][0] += (h > 0.f ? h : 0.f) * hw0;
            h = acc[mt][nt][1] + hb0; v[nt][1] += (h > 0.f ? h : 0.f) * hw0;
            h = acc[mt][nt][2] + hb1; v[nt][0] += (h > 0.f ? h : 0.f) * hw1;
            h = acc[mt][nt][3] + hb1; v[nt][1] += (h > 0.f ? h : 0.f) * hw1;
        }
    }
    #pragma unroll
    for (int nt = 0; nt < 4; nt++)
        #pragma unroll
        for (int par = 0; par < 2; par++) {
            float s = v[nt][par];
            s += __shfl_xor_sync(0xFFFFFFFFu, s, 4);
            s += __shfl_xor_sync(0xFFFFFFFFu, s, 8);
            s += __shfl_xor_sync(0xFFFFFFFFu, s, 16);
            v[nt][par] = s;
        }
    if (lane < 4) {
        #pragma unroll
        for (int nt = 0; nt < 4; nt++) {
            atomicAdd(&red[wn*32 + nt*8 + lane*2 + 0], v[nt][0]);
            atomicAdd(&red[wn*32 + nt*8 + lane*2 + 1], v[nt][1]);
        }
    }
    __syncthreads();
    if (tid < 64) {
        int pp = p0 + tid;
        if (pp < HWP) {
            float z = red[tid] + b2[0];
            g_sapx[(size_t)n*HWP + pp] = 1.f / (1.f + expf(-z));
        }
    }
}

// ---------------- threshold + PIXEL-ORDERED candidate compaction ----------------
__global__ __launch_bounds__(1024)
void k_thresh_cand(const float* __restrict__ dis) {
    int b = blockIdx.x;
    __shared__ unsigned int hist[8][256], histsum[256];
    __shared__ unsigned int sh_prefix;
    __shared__ int sh_R;
    __shared__ int warpsum[32];
    __shared__ int sh_base;
    int tid = threadIdx.x, lane = tid & 31, wid = tid >> 5;
    int wid8 = wid & 7;
    if (tid == 0) { sh_prefix = 0u; sh_R = SS; sh_base = 0; }
    for (int byte = 3; byte >= 0; byte--) {
        for (int i = tid; i < 8*256; i += 1024) ((unsigned int*)hist)[i] = 0u;
        __syncthreads();
        int shift = byte * 8;
        unsigned int pref = sh_prefix;
        for (int i = tid; i < HWP; i += 1024) {
            float vlo = fmaxf(g_sapx[(size_t)b*HWP + i] - MARG, 0.f) * dis[(size_t)b*HWP + i];
            unsigned int k = __float_as_uint(vlo);
            if (byte == 3 || (k >> (shift+8)) == (pref >> (shift+8)))
                atomicAdd(&hist[wid8][(k >> shift) & 0xFFu], 1u);
        }
        __syncthreads();
        if (tid < 256) {
            unsigned int s = 0;
            #pragma unroll
            for (int w = 0; w < 8; w++) s += hist[w][tid];
            histsum[tid] = s;
        }
        __syncthreads();
        if (tid == 0) {
            int R = sh_R; long long cum = 0; int chosen = 0;
            for (int v = 255; v >= 0; v--) {
                cum += histsum[v];
                if (cum >= R) { chosen = v; sh_R = R - (int)(cum - histsum[v]); break; }
            }
            sh_prefix = pref | ((unsigned int)chosen << shift);
        }
        __syncthreads();
    }
    unsigned int T = sh_prefix;
    for (int base = 0; base < HWP; base += 1024) {
        int p = base + tid;
        bool c = false;
        size_t i = (size_t)b*HWP + p;
        if (p < HWP) {
            float hi = (g_sapx[i] + MARG) * dis[i];
            c = (__float_as_uint(hi) >= T);
        }
        unsigned int bal = __ballot_sync(0xFFFFFFFFu, c);
        int wr = __popc(bal & ((1u << lane) - 1u));
        if (lane == 0) warpsum[wid] = __popc(bal);
        __syncthreads();
        if (tid < 32) {
            int v2 = warpsum[tid];
            #pragma unroll
            for (int off = 1; off < 32; off <<= 1) {
                int u = __shfl_up_sync(0xFFFFFFFFu, v2, off);
                if ((int)tid >= off) v2 += u;
            }
            warpsum[tid] = v2;   // inclusive scan
        }
        __syncthreads();
        int woff = (wid == 0) ? 0 : warpsum[wid - 1];
        if (c) {
            int slot = sh_base + woff + wr;
            if (slot < MAXC) { g_cand[b*MAXC + slot] = p; g_cslot[i] = slot; }
        }
        __syncthreads();
        if (tid == 0) sh_base += warpsum[31];
        __syncthreads();
    }
    if (tid == 0) g_ncand[b] = sh_base;
}

// ---------------- gather candidate columns compact (one block per candidate) ----------------
__global__ void k_gx(const float* __restrict__ x) {
    int b = blockIdx.y, s = blockIdx.x, c = threadIdx.x;
    int nc = min(g_ncand[b], MAXC);
    if (s >= nc) return;
    int pix = g_cand[b*MAXC + s];
    g_xc[((size_t)b*MAXC + s)*CC + c] = x[((size_t)b*CC + c)*HWP + pix];
}

// ================= PASS 2: exact fp32 SIMT score on candidates (B-prefetch) =================
__global__ __launch_bounds__(256, 2)
void k_score_exact(const float* __restrict__ w1, const float* __restrict__ b1,
                   const float* __restrict__ w2, const float* __restrict__ b2,
                   const float* __restrict__ dis)
{
    int b  = blockIdx.y;
    int c0 = blockIdx.x * 64;
    int nc = min(g_ncand[b], MAXC);
    if (c0 >= nc) return;
    __shared__ float As[KC][CC];
    __shared__ float Bs[KC][64];
    __shared__ float red[16][64];
    __shared__ int   sh_pix[64];
    int tid = threadIdx.x;
    int tx = tid & 15, ty = tid >> 4;
    if (tid < 64) sh_pix[tid] = (c0 + tid < nc) ? g_cand[b*MAXC + c0 + tid] : -1;

    int jj = tid >> 2, kq2 = (tid & 3) * 2;
    bool ok = (c0 + jj < nc);
    const float* xrow = &g_xc[((size_t)b*MAXC + c0 + jj)*CC];

    float acc[16][4];
    #pragma unroll
    for (int r = 0; r < 16; r++)
        #pragma unroll
        for (int j = 0; j < 4; j++) acc[r][j] = 0.f;

    // prefetch B chunk 0
    float4 pv0, pv1;
    pv0 = ok ? *(const float4*)(xrow + kq2*4)     : make_float4(0.f,0.f,0.f,0.f);
    pv1 = ok ? *(const float4*)(xrow + (kq2+1)*4) : make_float4(0.f,0.f,0.f,0.f);

    for (int k0 = 0; k0 < CC; k0 += KC) {
        for (int t = tid; t < CC * (KC/4); t += 256) {
            int d  = t >> 3, kq = t & 7;
            float4 v = *(const float4*)(w1 + (size_t)d * CC + k0 + kq*4);
            As[kq*4+0][d] = v.x; As[kq*4+1][d] = v.y;
            As[kq*4+2][d] = v.z; As[kq*4+3][d] = v.w;
        }
        {   // store prefetched B
            Bs[kq2*4+0][jj] = pv0.x; Bs[kq2*4+1][jj] = pv0.y;
            Bs[kq2*4+2][jj] = pv0.z; Bs[kq2*4+3][jj] = pv0.w;
            Bs[(kq2+1)*4+0][jj] = pv1.x; Bs[(kq2+1)*4+1][jj] = pv1.y;
            Bs[(kq2+1)*4+2][jj] = pv1.z; Bs[(kq2+1)*4+3][jj] = pv1.w;
        }
        __syncthreads();
        if (k0 + KC < CC) {   // prefetch next B chunk (overlaps fma phase)
            pv0 = ok ? *(const float4*)(xrow + k0 + KC + kq2*4)     : make_float4(0.f,0.f,0.f,0.f);
            pv1 = ok ? *(const float4*)(xrow + k0 + KC + (kq2+1)*4) : make_float4(0.f,0.f,0.f,0.f);
        }
        #pragma unroll
        for (int kk = 0; kk < KC; kk++) {
            float a[16];
            *(float4*)(a+0)  = *(float4*)&As[kk][ty*16+0];
            *(float4*)(a+4)  = *(float4*)&As[kk][ty*16+4];
            *(float4*)(a+8)  = *(float4*)&As[kk][ty*16+8];
            *(float4*)(a+12) = *(float4*)&As[kk][ty*16+12];
            float4 bf = *(float4*)&Bs[kk][tx*4];
            float bb[4] = {bf.x, bf.y, bf.z, bf.w};
            #pragma unroll
            for (int r = 0; r < 16; r++)
                #pragma unroll
                for (int j = 0; j < 4; j++) acc[r][j] += a[r] * bb[j];
        }
        __syncthreads();
    }
    float part[4] = {0.f, 0.f, 0.f, 0.f};
    #pragma unroll
    for (int r = 0; r < 16; r++) {
        int d = ty*16 + r;
        float bbv = b1[d], wwv = w2[d];
        #pragma unroll
        for (int j = 0; j < 4; j++) {
            float h = acc[r][j] + bbv;
            h = h > 0.f ? h : 0.f;
            part[j] += h * wwv;
        }
    }
    #pragma unroll
    for (int j = 0; j < 4; j++) red[ty][tx*4+j] = part[j];
    __syncthreads();
    if (tid < 64) {
        int pix = sh_pix[tid];
        if (pix >= 0) {
            float s = 0.f;
            #pragma unroll
            for (int r = 0; r < 16; r++) s += red[r][tid];
            float z  = s + b2[0];
            float sc = 1.f / (1.f + expf(-z));
            sc *= dis[(size_t)b*HWP + pix];
            unsigned int bits = __float_as_uint(sc);
            g_ckeys[b*MAXC + c0 + tid] =
                ((unsigned long long)bits << 32) | (unsigned int)(~(unsigned int)pix);
        }
    }
}

// ---------------- bitonic ascending sort ----------------
__device__ __forceinline__ void bitonic_asc(unsigned long long* buf, int n, int tid, int nth) {
    for (int k2 = 2; k2 <= n; k2 <<= 1)
        for (int j = k2 >> 1; j > 0; j >>= 1) {
            __syncthreads();
            for (int i = tid; i < n; i += nth) {
                int ixj = i ^ j;
                if (ixj > i) {
                    unsigned long long a = buf[i], b = buf[ixj];
                    bool up = ((i & k2) == 0);
                    if (up ? (a > b) : (a < b)) { buf[i] = b; buf[ixj] = a; }
                }
            }
        }
    __syncthreads();
}

// ---------------- exact top-S over compact candidate keys ----------------
__global__ __launch_bounds__(1024)
void k_topk_c() {
    int b = blockIdx.x;
    int nc = min(g_ncand[b], MAXC);
    const unsigned long long* keys = g_ckeys + (size_t)b * MAXC;
    __shared__ unsigned int hist[8][256], histsum[256];
    __shared__ unsigned long long sh_prefix;
    __shared__ int sh_R, sh_cnt;
    __shared__ unsigned long long buf[4096];
    int tid = threadIdx.x, wid8 = (tid >> 5) & 7;
    if (tid == 0) { sh_prefix = 0ULL; sh_R = SS; sh_cnt = 0; }

    for (int byte = 7; byte >= 0; byte--) {
        for (int i = tid; i < 8*256; i += 1024) ((unsigned int*)hist)[i] = 0u;
        __syncthreads();
        int shift = byte * 8;
        unsigned long long pref = sh_prefix;
        for (int i = tid; i < nc; i += 1024) {
            unsigned long long k = keys[i];
            if (byte == 7 || (k >> (shift+8)) == (pref >> (shift+8)))
                atomicAdd(&hist[wid8][(unsigned)(k >> shift) & 0xFFu], 1u);
        }
        __syncthreads();
        if (tid < 256) {
            unsigned int s = 0;
            #pragma unroll
            for (int w = 0; w < 8; w++) s += hist[w][tid];
            histsum[tid] = s;
        }
        __syncthreads();
        if (tid == 0) {
            int R = sh_R; long long cum = 0; int chosen = 0;
            for (int v = 255; v >= 0; v--) {
                cum += histsum[v];
                if (cum >= R) { chosen = v; sh_R = R - (int)(cum - histsum[v]); break; }
            }
            sh_prefix = pref | ((unsigned long long)chosen << shift);
        }
        __syncthreads();
    }
    unsigned long long T = sh_prefix;
    for (int i = tid; i < 4096; i += 1024) buf[i] = 0ULL;
    __syncthreads();
    for (int i = tid; i < nc; i += 1024) {
        unsigned long long k = keys[i];
        if (k >= T) { int pos = atomicAdd(&sh_cnt, 1); if (pos < 4096) buf[pos] = k; }
    }
    __syncthreads();
    bitonic_asc(buf, 4096, tid, 1024);
    for (int s = tid; s < SS; s += 1024) {
        unsigned long long k = buf[4095 - s];
        g_topidx[b*SS + s] = (int)(~(unsigned int)k);
        g_conf  [b*SS + s] = __uint_as_float((unsigned int)(k >> 32));
    }
}

// ---------------- gather (compact) + layernorm + *conf + fp16x2 split + sumsq ----------------
__global__ void k_gather_ln() {
    int b = blockIdx.y, s = blockIdx.x;
    int c = threadIdx.x;
    __shared__ float sh[256];
    int   pix  = g_topidx[b*SS + s];
    float conf = g_conf[b*SS + s];
    int   slot = g_cslot[b*HWP + pix];
    float v = g_xc[((size_t)b*MAXC + slot)*CC + c];

    sh[c] = v; __syncthreads();
    for (int st = 128; st > 0; st >>= 1) { if (c < st) sh[c] += sh[c+st]; __syncthreads(); }
    float mu = sh[0] * (1.f/256.f);
    __syncthreads();
    float dv = v - mu;
    sh[c] = dv * dv; __syncthreads();
    for (int st = 128; st > 0; st >>= 1) { if (c < st) sh[c] += sh[c+st]; __syncthreads(); }
    float var = sh[0] * (1.f/256.f);
    __syncthreads();
    float t = dv / sqrtf(var + 1e-5f) * conf;
    size_t o = ((size_t)b*SSP + s)*CC + c;
    g_tokens[o] = t;
    __half t1 = __float2half(t);
    __half t2 = __float2half(t - __half2float(t1));
    g_tspH[0][o] = t1; g_tspH[1][o] = t2;
    sh[c] = t * t; __syncthreads();
    for (int st = 128; st > 0; st >>= 1) { if (c < st) sh[c] += sh[c+st]; __syncthreads(); }
    if (c == 0) g_sq[b*SS + s] = sh[0];
}

// ================= distance GEMM: fp16x2 (3 terms), cp.async, fused partial-KNN =================
#define DI_T  (128*KP*2)             // 10240 B per split tile
#define DI_STG (4*DI_T)              // 40960 per stage
#define DI_SMEM (2*DI_STG)           // 81920 (Dt 66048 + sm_part 10240 fit)
#define NPAIR (NTIL*(NTIL+1)/2)      // 210

__global__ __launch_bounds__(256, 2)
void k_dist_mma() {
    int b = blockIdx.y;
    int t = blockIdx.x;
    int bi = (int)((sqrtf(8.f*t + 1.f) - 1.f) * 0.5f);
    while ((bi+1)*(bi+2)/2 <= t) bi++;
    while (bi*(bi+1)/2 > t) bi--;
    int bj = t - bi*(bi+1)/2;
    extern __shared__ char smp[];
    __shared__ float s_sqi[128], s_sqj[128], wmaxs[8];
    int tid = threadIdx.x, lane = tid & 31, wid = tid >> 5;
    int g = lane >> 2, tg = lane & 3;
    int wm = wid & 1, wn = wid >> 1;
    int i0 = bi * 128, j0 = bj * 128;
    uint32_t sbase = smem_u32(smp);

    if (tid < 128)      s_sqi[tid]     = (i0 + tid     < SS) ? g_sq[b*SS + i0 + tid]     : 0.f;
    else                s_sqj[tid-128] = (j0 + tid-128 < SS) ? g_sq[b*SS + j0 + tid-128] : 0.f;

    int r = tid & 127, side = tid >> 7;
    int grow = (side ? j0 : i0) + r;
    #pragma unroll
    for (int s = 0; s < 2; s++) {
        const char* src = (const char*)(&g_tspH[s][((size_t)(b*SSP + grow))*CC]);
        uint32_t dst = sbase + (side*2 + s)*DI_T + r*(KP*2);
        #pragma unroll
        for (int q = 0; q < 4; q++) cp16(dst + q*16, src + q*16);
    }
    CP_COMMIT();

    float acc[4][4][4];
    #pragma unroll
    for (int mt = 0; mt < 4; mt++)
        #pragma unroll
        for (int nt = 0; nt < 4; nt++)
            #pragma unroll
            for (int rr = 0; rr < 4; rr++) acc[mt][nt][rr] = 0.f;

    const int TA[3] = {0,0,1};
    const int TB[3] = {0,1,0};

    for (int c = 0; c < CC/KC; c++) {
        int stg = c & 1;
        if (c + 1 < CC/KC) {
            int nstg = stg ^ 1;
            #pragma unroll
            for (int s = 0; s < 2; s++) {
                const char* src = (const char*)(&g_tspH[s][((size_t)(b*SSP + grow))*CC + (c+1)*KC]);
                uint32_t dst = sbase + nstg*DI_STG + (side*2 + s)*DI_T + r*(KP*2);
                #pragma unroll
                for (int q = 0; q < 4; q++) cp16(dst + q*16, src + q*16);
            }
            CP_COMMIT();
            CP_WAIT(1);
        } else {
            CP_WAIT(0);
        }
        __syncthreads();
        const char* base = smp + stg*DI_STG;
        #pragma unroll
        for (int term = 0; term < 3; term++) {
            int sa = TA[term], sb = TB[term];
            #pragma unroll
            for (int ks = 0; ks < 2; ks++) {
                uint32_t af[4][4], bf[4][2];
                const char* Ab = base + sa*DI_T + ks*32 + tg*4;
                #pragma unroll
                for (int mt = 0; mt < 4; mt++) {
                    const char* pA = Ab + (wm*64 + mt*16 + g)*(KP*2);
                    af[mt][0] = *(const uint32_t*)pA;
                    af[mt][1] = *(const uint32_t*)(pA + 8*(KP*2));
                    af[mt][2] = *(const uint32_t*)(pA + 16);
                    af[mt][3] = *(const uint32_t*)(pA + 8*(KP*2) + 16);
                }
                const char* Bb = base + (2 + sb)*DI_T + ks*32 + tg*4;
                #pragma unroll
                for (int nt = 0; nt < 4; nt++) {
                    const char* pB = Bb + (wn*32 + nt*8 + g)*(KP*2);
                    bf[nt][0] = *(const uint32_t*)pB;
                    bf[nt][1] = *(const uint32_t*)(pB + 16);
                }
                #pragma unroll
                for (int mt = 0; mt < 4; mt++)
                    #pragma unroll
                    for (int nt = 0; nt < 4; nt++)
                        mma_f16(acc[mt][nt], af[mt], bf[nt]);
            }
        }
        __syncthreads();
    }

    float* Dt = (float*)smp;   // [128][129] = 66048 B
    float* sm_part = (float*)(smp + 66048);  // [256][10] = 10240 B
    float tmax = 0.f;
    #pragma unroll
    for (int mt = 0; mt < 4; mt++) {
        #pragma unroll
        for (int nt = 0; nt < 4; nt++) {
            int il0 = wm*64 + mt*16 + g;
            int jl0 = wn*32 + nt*8 + tg*2;
            #pragma unroll
            for (int rr = 0; rr < 4; rr++) {
                int il = il0 + ((rr >> 1) ? 8 : 0);
                int jl = jl0 + (rr & 1);
                float d2 = s_sqi[il] + s_sqj[jl] - 2.f * acc[mt][nt][rr];
                float d  = sqrtf(fmaxf(d2, 1e-12f)) * 0.0625f;
                Dt[il*129 + jl] = d;
                if (i0 + il < SS && j0 + jl < SS) tmax = fmaxf(tmax, d);
            }
        }
    }
    __syncthreads();
    for (int idx = tid; idx < 128*128; idx += 256) {
        int il = idx >> 7, jj = idx & 127;
        int i = i0 + il, j = j0 + jj;
        if (i < SS && j < SS) g_dist[((size_t)b*SS + i)*SS + j] = Dt[il*129 + jj];
    }
    if (bi != bj) {
        for (int idx = tid; idx < 128*128; idx += 256) {
            int jl = idx >> 7, ii = idx & 127;
            int i = i0 + ii, j = j0 + jl;
            if (i < SS) g_dist[((size_t)b*SS + j)*SS + i] = Dt[ii*129 + jl];
        }
    }

    // ---- fused partial top-10: i-side rows, tile column bj ----
    {
        int row = tid >> 1, half = tid & 1;
        float tp[KNNK];
        #pragma unroll
        for (int q = 0; q < KNNK; q++) tp[q] = 3.4e38f;
        if (i0 + row < SS) {
            const float* drow = Dt + row*129 + half*64;
            for (int jj = 0; jj < 64; jj++) {
                int jl = half*64 + jj;
                float d = (j0 + jl < SS) ? drow[jj] : 3.4e38f;
                ins10(tp, d);
            }
        }
        #pragma unroll
        for (int q = 0; q < KNNK; q++) sm_part[tid*KNNK + q] = tp[q];
        __syncwarp();
        if (half == 0 && i0 + row < SS) {
            const float* a  = &sm_part[tid*KNNK];
            const float* bq = &sm_part[(tid+1)*KNNK];
            float* dst = &g_knnpart[(((size_t)b*SS + i0 + row)*NTIL + bj)*KNNK];
            int ia = 0, ib = 0;
            #pragma unroll
            for (int q = 0; q < KNNK; q++) {
                float va = a[ia], vb = bq[ib];
                if (va <= vb) { dst[q] = va; ia++; } else { dst[q] = vb; ib++; }
            }
        }
    }
    // ---- mirror side: j-rows, tile column bi (only off-diagonal) ----
    if (bi != bj) {
        __syncthreads();
        int row = tid >> 1, half = tid & 1;   // row = jl ; j always < SS (bj <= 18)
        float tp[KNNK];
        #pragma unroll
        for (int q = 0; q < KNNK; q++) tp[q] = 3.4e38f;
        for (int ii = 0; ii < 64; ii++) {
            int il = half*64 + ii;
            float d = (i0 + il < SS) ? Dt[il*129 + row] : 3.4e38f;
            ins10(tp, d);
        }
        #pragma unroll
        for (int q = 0; q < KNNK; q++) sm_part[tid*KNNK + q] = tp[q];
        __syncwarp();
        if (half == 0) {
            const float* a  = &sm_part[tid*KNNK];
            const float* bq = &sm_part[(tid+1)*KNNK];
            float* dst = &g_knnpart[(((size_t)b*SS + j0 + row)*NTIL + bi)*KNNK];
            int ia = 0, ib = 0;
            #pragma unroll
            for (int q = 0; q < KNNK; q++) {
                float va = a[ia], vb = bq[ib];
                if (va <= vb) { dst[q] = va; ia++; } else { dst[q] = vb; ib++; }
            }
        }
    }

    #pragma unroll
    for (int off = 16; off; off >>= 1) tmax = fmaxf(tmax, __shfl_xor_sync(0xFFFFFFFFu, tmax, off));
    if (lane == 0) wmaxs[wid] = tmax;
    __syncthreads();
    if (tid == 0) {
        float m = 0.f;
        #pragma unroll
        for (int w = 0; w < 8; w++) m = fmaxf(m, wmaxs[w]);
        atomicMax(&g_distmax[b], __float_as_uint(m));
    }
}

// ---------------- KNN density: merge per-tile partials (16 MB read) ----------------
__global__ void k_knn_merge() {
    int gw = (blockIdx.x * blockDim.x + threadIdx.x) >> 5;
    int lane = threadIdx.x & 31;
    if (gw >= NS) return;
    const float* part = g_knnpart + (size_t)gw * (NTIL*KNNK);
    float top[KNNK];
    #pragma unroll
    for (int t = 0; t < KNNK; t++) top[t] = 3.4e38f;
    for (int idx = lane; idx < NTIL*KNNK; idx += 32) {
        float d = part[idx];
        ins10(top, d);
    }
    int ptr = 0;
    float sumsq = 0.f;
    for (int t = 0; t < KNNK; t++) {
        float cand = (ptr < KNNK) ? top[ptr] : 3.4e38f;
        float m = cand;
        #pragma unroll
        for (int off = 16; off; off >>= 1) m = fminf(m, __shfl_xor_sync(0xFFFFFFFFu, m, off));
        sumsq += m * m;
        unsigned bal = __ballot_sync(0xFFFFFFFFu, cand == m);
        int src = __ffs(bal) - 1;
        if (lane == src) ptr++;
    }
    if (lane == 0)
        g_density[gw] = expf(-(sumsq * (1.f/KNNK))) + g_noise[gw] * 1e-6f;
}

// ---------------- parent distance + cscore (warp per row, float4, 2-way ILP) ----------------
__global__ void k_parent() {
    int gw = (blockIdx.x * blockDim.x + threadIdx.x) >> 5;
    int lane = threadIdx.x & 31;
    if (gw >= NS) return;
    int b = gw / SS, i = gw % SS;
    float di   = g_density[gw];
    float dmax = __uint_as_float(g_distmax[b]);
    const float4* row4  = (const float4*)(g_dist + ((size_t)b*SS + i)*SS);
    const float4* dens4 = (const float4*)(g_density + b*SS);
    float acc0 = dmax, acc1 = dmax;
    int j4 = lane;
    for (; j4 + 32 < SS/4; j4 += 64) {
        float4 dv0 = dens4[j4],      rv0 = row4[j4];
        float4 dv1 = dens4[j4 + 32], rv1 = row4[j4 + 32];
        if (dv0.x > di) acc0 = fminf(acc0, rv0.x);
        if (dv0.y > di) acc0 = fminf(acc0, rv0.y);
        if (dv0.z > di) acc0 = fminf(acc0, rv0.z);
        if (dv0.w > di) acc0 = fminf(acc0, rv0.w);
        if (dv1.x > di) acc1 = fminf(acc1, rv1.x);
        if (dv1.y > di) acc1 = fminf(acc1, rv1.y);
        if (dv1.z > di) acc1 = fminf(acc1, rv1.z);
        if (dv1.w > di) acc1 = fminf(acc1, rv1.w);
    }
    if (j4 < SS/4) {
        float4 dv = dens4[j4], rv = row4[j4];
        if (dv.x > di) acc0 = fminf(acc0, rv.x);
        if (dv.y > di) acc0 = fminf(acc0, rv.y);
        if (dv.z > di) acc0 = fminf(acc0, rv.z);
        if (dv.w > di) acc0 = fminf(acc0, rv.w);
    }
    float acc = fminf(acc0, acc1);
    #pragma unroll
    for (int off = 16; off; off >>= 1) acc = fminf(acc, __shfl_xor_sync(0xFFFFFFFFu, acc, off));
    if (lane == 0) g_cscore[gw] = acc * di;
}

// ---------------- cluster centers ----------------
__global__ __launch_bounds__(1024)
void k_centers() {
    int b = blockIdx.x;
    __shared__ unsigned long long buf[4096];
    int tid = threadIdx.x;
    for (int i = tid; i < 4096; i += 1024) {
        unsigned long long key = 0ULL;
        if (i < SS) {
            unsigned int bits = __float_as_uint(g_cscore[b*SS + i]);
            key = ((unsigned long long)bits << 32) | (unsigned int)(~(unsigned int)i);
        }
        buf[i] = key;
    }
    __syncthreads();
    bitonic_asc(buf, 4096, tid, 1024);
    for (int k = tid; k < KCL; k += 1024) {
        unsigned long long key = buf[4095 - k];
        g_centers[b*KCL + k] = (int)(~(unsigned int)key);
    }
}

// ---------------- cluster assignment + pixcl + weights (fused) ----------------
__global__ void k_assign() {
    int b = blockIdx.y;
    int s = blockIdx.x * blockDim.x + threadIdx.x;
    __shared__ int cs[KCL];
    for (int t = threadIdx.x; t < KCL; t += blockDim.x) cs[t] = g_centers[b*KCL + t];
    __syncthreads();
    if (s >= SS) return;
    float best = 3.4e38f; int bk = 0, ovr = -1;
    for (int k = 0; k < KCL; k++) {
        int ck = cs[k];
        if (ck == s) ovr = k;
        float d = g_dist[((size_t)b*SS + ck)*SS + s];
        if (d < best) { best = d; bk = k; }
    }
    int cl = (ovr >= 0) ? ovr : bk;
    g_cluster[b*SS + s] = cl;
    g_pixcl[b*HWP + g_topidx[b*SS + s]] = cl;
    atomicAdd(&g_allw[b*KCL + cl], g_conf[b*SS + s]);
}

// ---------------- merge ----------------
__global__ void k_merge() {
    int b = blockIdx.y, s = blockIdx.x, c = threadIdx.x;
    int cl = g_cluster[b*SS + s];
    float nw = g_conf[b*SS + s] / (g_allw[b*KCL + cl] + 1e-6f);
    atomicAdd(&g_merged[((size_t)b*KCL + cl)*CC + c],
              g_tokens[((size_t)b*SSP + s)*CC + c] * nw);
}

// ---------------- fused final write (float4) ----------------
__global__ void k_finalize(const float* __restrict__ x, float* __restrict__ out) {
    size_t q = (size_t)blockIdx.x * blockDim.x + threadIdx.x;   // float4 index
    if (q >= (size_t)NN * CC * HWP / 4) return;
    size_t idx = q * 4;
    int b   = (int)(idx / ((size_t)CC * HWP));
    int rem = (int)(idx % ((size_t)CC * HWP));
    int c   = rem / HWP;
    int p   = rem % HWP;        // p % 4 == 0 (HWP divisible by 4)
    float4 v;
    if (g_isego[b]) v = *(const float4*)(x + idx);
    else {
        const int4 cl4 = *(const int4*)(g_pixcl + b*HWP + p);
        const float* mb = g_merged + (size_t)b*KCL*CC + c;
        v.x = (cl4.x >= 0) ? mb[(size_t)cl4.x*CC] : 0.f;
        v.y = (cl4.y >= 0) ? mb[(size_t)cl4.y*CC] : 0.f;
        v.z = (cl4.z >= 0) ? mb[(size_t)cl4.z*CC] : 0.f;
        v.w = (cl4.w >= 0) ? mb[(size_t)cl4.w*CC] : 0.f;
    }
    *(float4*)(out + idx) = v;
}

// ---------------- launch ----------------
extern "C" void kernel_launch(void* const* d_in, const int* in_sizes, int n_in,
                              void* d_out, int out_size) {
    const float* x   = (const float*)d_in[0];
    const float* w1  = (const float*)d_in[1];
    const float* b1  = (const float*)d_in[2];
    const float* w2  = (const float*)d_in[3];
    const float* b2  = (const float*)d_in[4];
    const float* dis = (const float*)d_in[5];
    const int*   rl  = (const int*)d_in[6];
    int nrec = in_sizes[6];
    float* out = (float*)d_out;

    static int attr_set = 0;
    if (!attr_set) {
        cudaFuncSetAttribute(k_dist_mma, cudaFuncAttributeMaxDynamicSharedMemorySize, DI_SMEM);
        attr_set = 1;
    }

    k_init<<<(NN*KCL*CC/4 + 255)/256, 256>>>(w1, rl, nrec);
    k_score_apx<<<dim3((HWP + 63)/64, NN), 256>>>(x, b1, w2, b2);
    k_thresh_cand<<<NN, 1024>>>(dis);
    k_gx<<<dim3(MAXC, NN), 256>>>(x);
    k_score_exact<<<dim3(MAXC/64, NN), 256>>>(w1, b1, w2, b2, dis);
    k_topk_c<<<NN, 1024>>>();
    k_gather_ln<<<dim3(SS, NN), 256>>>();
    k_dist_mma<<<dim3(NPAIR, NN), 256, DI_SMEM>>>();
    k_knn_merge<<<(NS*32 + 255)/256, 256>>>();
    k_parent<<<(NS*32 + 255)/256, 256>>>();
    k_centers<<<NN, 1024>>>();
    k_assign<<<dim3((SS + 255)/256, NN), 256>>>();
    k_merge<<<dim3(SS, NN), 256>>>();
    k_finalize<<<(unsigned)(((size_t)NN*CC*HWP/4 + 255)/256), 256>>>(x, out);
}